// round 8
// baseline (speedup 1.0000x reference)
#include <cuda_runtime.h>

#define B   64
#define T   100
#define NI  700
#define NH  512
#define NO  20
#define TAUc 0.6f
#define KAPc 0.6f
#define THRc 0.6f
#define LRc  0.05f

// ---------------- persistent device scratch ----------------
__device__ float g_XP  [T*B*NH];   // x @ W1^T, rows m = t*B+b
__device__ float g_TIN [T*B*NI];
__device__ float g_TREC[T*B*NH];
__device__ float g_HT  [T*B*NH];
__device__ float g_Z   [T*B*NH];
__device__ float g_EF  [T*B*NO];
__device__ float g_A   [T*B*NH];
__device__ float g_gpart[8*512*700];

// forward smem layout (dynamic): ws[NO*NH] | zsh[NH] | errh[T*NO] | list[NH] | wcnt[16]
#define FWD_SMEM ((NO*NH + NH + T*NO + 16) * 4 + NH * 4)

// ---------------- tin scan (no recurrence) ----------------
__global__ void k_tin(const float* __restrict__ x) {
    int n = blockIdx.x * blockDim.x + threadIdx.x;
    if (n >= B * NI) return;
    int b = n / NI, i = n - b * NI;
    float tv = 0.f;
    for (int t = 0; t < T; t++) {
        tv = TAUc * tv + x[(b * T + t) * NI + i];
        g_TIN[((size_t)t * B + b) * NI + i] = tv;
    }
}

// ---------------- Xproj = X @ W1^T : [6400,512], K=700, fp32 SIMT ----------------
// PRECISION-CRITICAL: feeds the spike threshold. Must stay bitwise-identical to
// the passing round-6 kernel (fp32, same summation order).
__global__ __launch_bounds__(256) void k_gemmX(const float* __restrict__ x,
                                               const float* __restrict__ w1) {
    __shared__ float As[16][129];
    __shared__ float Bs[16][129];
    int m0 = blockIdx.y * 128, n0 = blockIdx.x * 128;
    int tid = threadIdx.x, tx = tid & 15, ty = tid >> 4;
    float acc[8][8] = {};

    for (int k0 = 0; k0 < NI; k0 += 16) {
#pragma unroll
        for (int rep = 0; rep < 2; rep++) {
            int f = tid + rep * 256;
            int mm = f >> 2, kq = f & 3;
            int kg = k0 + kq * 4;
            {
                int m = m0 + mm, t = m >> 6, b = m & 63;
                const float* xp = &x[((size_t)b * T + t) * NI + kg];
                float4 v;
                if (kg + 3 < NI) v = *(const float4*)xp;
                else {
                    v.x = (kg + 0 < NI) ? xp[0] : 0.f;
                    v.y = (kg + 1 < NI) ? xp[1] : 0.f;
                    v.z = (kg + 2 < NI) ? xp[2] : 0.f;
                    v.w = (kg + 3 < NI) ? xp[3] : 0.f;
                }
                As[kq * 4 + 0][mm] = v.x; As[kq * 4 + 1][mm] = v.y;
                As[kq * 4 + 2][mm] = v.z; As[kq * 4 + 3][mm] = v.w;
            }
            {
                int n = n0 + mm;
                const float* wp = &w1[(size_t)n * NI + kg];
                float4 v;
                if (kg + 3 < NI) v = *(const float4*)wp;
                else {
                    v.x = (kg + 0 < NI) ? wp[0] : 0.f;
                    v.y = (kg + 1 < NI) ? wp[1] : 0.f;
                    v.z = (kg + 2 < NI) ? wp[2] : 0.f;
                    v.w = (kg + 3 < NI) ? wp[3] : 0.f;
                }
                Bs[kq * 4 + 0][mm] = v.x; Bs[kq * 4 + 1][mm] = v.y;
                Bs[kq * 4 + 2][mm] = v.z; Bs[kq * 4 + 3][mm] = v.w;
            }
        }
        __syncthreads();
#pragma unroll
        for (int k = 0; k < 16; k++) {
            float a[8], bb[8];
#pragma unroll
            for (int i = 0; i < 4; i++) {
                a[i]      = As[k][ty * 4 + i];
                a[4 + i]  = As[k][64 + ty * 4 + i];
                bb[i]     = Bs[k][tx * 4 + i];
                bb[4 + i] = Bs[k][64 + tx * 4 + i];
            }
#pragma unroll
            for (int i = 0; i < 8; i++)
#pragma unroll
                for (int j = 0; j < 8; j++) acc[i][j] += a[i] * bb[j];
        }
        __syncthreads();
    }
#pragma unroll
    for (int i = 0; i < 8; i++) {
        int m = m0 + ((i < 4) ? ty * 4 + i : 64 + ty * 4 + (i - 4));
#pragma unroll
        for (int j = 0; j < 8; j++) {
            int n = n0 + ((j < 4) ? tx * 4 + j : 64 + tx * 4 + (j - 4));
            g_XP[(size_t)m * NH + n] = acc[i][j];
        }
    }
}

// ---------------- tf32 helpers ----------------
__device__ __forceinline__ unsigned f2tf(float f) {
    unsigned u; asm("cvt.rna.tf32.f32 %0, %1;" : "=r"(u) : "f"(f)); return u;
}
__device__ __forceinline__ void mma1688(float* d, const unsigned* a, const unsigned* b) {
    asm volatile("mma.sync.aligned.m16n8k8.row.col.f32.tf32.tf32.f32 "
        "{%0,%1,%2,%3}, {%4,%5,%6,%7}, {%8,%9}, {%0,%1,%2,%3};"
        : "+f"(d[0]), "+f"(d[1]), "+f"(d[2]), "+f"(d[3])
        : "r"(a[0]), "r"(a[1]), "r"(a[2]), "r"(a[3]), "r"(b[0]), "r"(b[1]));
}

#define SMS 136   // smem stride: 136 mod 32 = 8 -> conflict-free fragment LDS

// ---------------- tf32 3x-split GEMM: C[M,N] = A^T B (gradients only) ----------------
// A: [K, M] row-major (stride sA). B: [K, N] row-major (stride sB).
// Block tile 128x128, warp tile 64x32 (2x4 warps), k-tile 16.
// 3x split (Ah*Bh + Ah*Bl + Al*Bh) -> ~fp32 accuracy, terminal outputs only.
__global__ __launch_bounds__(256) void k_mma(const float* __restrict__ A, int sA,
                                             const float* __restrict__ Bm, int sB,
                                             float* __restrict__ Cp,
                                             int M, int N, int kchunk) {
    __shared__ unsigned Ah[16][SMS], Al[16][SMS], Bh[16][SMS], Bl[16][SMS];
    int m0 = blockIdx.y * 128, n0 = blockIdx.x * 128;
    int k0s = blockIdx.z * kchunk;
    int tid = threadIdx.x, lane = tid & 31, warp = tid >> 5;
    int wm = warp & 1, wn = warp >> 1;
    int g = lane >> 2, tg = lane & 3;

    float acc[4][4][4] = {};

    for (int k0 = k0s; k0 < k0s + kchunk; k0 += 16) {
        int kk = tid >> 4, c = (tid & 15) * 8;
        // stage A [K,M]: M multiple of 128, k always in-range (kchunk | Kend)
        {
            const float* ap = A + (size_t)(k0 + kk) * sA + m0 + c;
            float4 v0 = *(const float4*)ap;
            float4 v1 = *(const float4*)(ap + 4);
            float vv[8] = {v0.x, v0.y, v0.z, v0.w, v1.x, v1.y, v1.z, v1.w};
#pragma unroll
            for (int u = 0; u < 8; u++) {
                unsigned h = f2tf(vv[u]);
                Ah[kk][c + u] = h;
                Al[kk][c + u] = f2tf(vv[u] - __uint_as_float(h));
            }
        }
        // stage B [K,N]: guard n
        {
            const float* bp = Bm + (size_t)(k0 + kk) * sB + n0 + c;
            float vv[8];
#pragma unroll
            for (int u = 0; u < 8; u++)
                vv[u] = (n0 + c + u < N) ? bp[u] : 0.f;
#pragma unroll
            for (int u = 0; u < 8; u++) {
                unsigned h = f2tf(vv[u]);
                Bh[kk][c + u] = h;
                Bl[kk][c + u] = f2tf(vv[u] - __uint_as_float(h));
            }
        }
        __syncthreads();

#pragma unroll
        for (int ks = 0; ks < 16; ks += 8) {
            unsigned ah[4][4], al[4][4], bh[4][2], bl[4][2];
#pragma unroll
            for (int i = 0; i < 4; i++) {
                int mi = wm * 64 + i * 16 + g;
                ah[i][0] = Ah[ks + tg][mi];     ah[i][1] = Ah[ks + tg][mi + 8];
                ah[i][2] = Ah[ks + tg + 4][mi]; ah[i][3] = Ah[ks + tg + 4][mi + 8];
                al[i][0] = Al[ks + tg][mi];     al[i][1] = Al[ks + tg][mi + 8];
                al[i][2] = Al[ks + tg + 4][mi]; al[i][3] = Al[ks + tg + 4][mi + 8];
            }
#pragma unroll
            for (int j = 0; j < 4; j++) {
                int nj = wn * 32 + j * 8 + g;
                bh[j][0] = Bh[ks + tg][nj]; bh[j][1] = Bh[ks + tg + 4][nj];
                bl[j][0] = Bl[ks + tg][nj]; bl[j][1] = Bl[ks + tg + 4][nj];
            }
#pragma unroll
            for (int i = 0; i < 4; i++)
#pragma unroll
                for (int j = 0; j < 4; j++) {
                    mma1688(acc[i][j], ah[i], bh[j]);
                    mma1688(acc[i][j], ah[i], bl[j]);
                    mma1688(acc[i][j], al[i], bh[j]);
                }
        }
        __syncthreads();
    }

    float* C = Cp + (size_t)blockIdx.z * M * N;
#pragma unroll
    for (int i = 0; i < 4; i++) {
#pragma unroll
        for (int j = 0; j < 4; j++) {
            int m = m0 + wm * 64 + i * 16 + g;
            int n = n0 + wn * 32 + j * 8 + tg * 2;
            if (n < N)     C[(size_t)m * N + n]           = acc[i][j][0];
            if (n + 1 < N) C[(size_t)m * N + n + 1]       = acc[i][j][1];
            if (n < N)     C[(size_t)(m + 8) * N + n]     = acc[i][j][2];
            if (n + 1 < N) C[(size_t)(m + 8) * N + n + 1] = acc[i][j][3];
        }
    }
}

// ---------------- forward: one block per sample, compacted spike list ----------------
__global__ __launch_bounds__(640) void k_forward(const float* __restrict__ wrec,
                                                 const float* __restrict__ wout,
                                                 const float* __restrict__ label,
                                                 float* __restrict__ out) {
    extern __shared__ float sm[];
    float* ws   = sm;                       // NO*NH
    float* zsh  = ws + NO * NH;             // NH
    float* errh = zsh + NH;                 // T*NO
    int*   list = (int*)(errh + T * NO);    // NH
    int*   wcnt = list + NH;                // 16

    int b = blockIdx.x;
    int tid = threadIdx.x, lane = tid & 31, w = tid >> 5;
    bool is_n = (tid < NH);
    int ow = w - 16;

    for (int i = tid; i < NO * NH; i += 640) ws[i] = wout[i];
    if (tid < NH) zsh[tid] = 0.f;
    if (tid < 16) wcnt[tid] = 0;
    __syncthreads();

    float hm = 0.f, tr = 0.f, zs = 0.f;
    float om[5] = {}, os[5] = {};
    int nact = 0;

    auto do_out = [&](int tp) {
#pragma unroll
        for (int q = 0; q < 5; q++) {
            int o = ow * 5 + q;
            float s = 0.f;
#pragma unroll
            for (int c = 0; c < 16; c++)
                s += zsh[c * 32 + lane] * ws[o * NH + c * 32 + lane];
#pragma unroll
            for (int off = 16; off; off >>= 1) s += __shfl_xor_sync(0xffffffffu, s, off);
            om[q] = TAUc * om[q] * (1.f - os[q]) + s;
            os[q] = (om[q] >= THRc) ? 1.f : 0.f;
            if (lane == 0) {
                out[((size_t)b * T + tp) * NO + o] = os[q];
                errh[tp * NO + o] = os[q] - label[((size_t)b * T + tp) * NO + o];
            }
        }
    };

    for (int t = 0; t < T; t++) {
        float z = 0.f, ht = 0.f;
        if (is_n) {
            float xp = __ldg(&g_XP[((size_t)t * B + b) * NH + tid]);
            float acc = 0.f;
            for (int i = 0; i < nact; i += 16) {
                float v[16];
#pragma unroll
                for (int u = 0; u < 16; u++) {
                    int ix = i + u;
                    v[u] = (ix < nact) ? __ldg(&wrec[(size_t)list[ix] * NH + tid]) : 0.f;
                }
#pragma unroll
                for (int u = 0; u < 16; u++) acc += v[u];
            }
            hm = TAUc * hm * (1.f - zs) + xp + acc;
            z  = (hm >= THRc) ? 1.f : 0.f;
            ht = TAUc * fmaxf(0.f, 1.f - fabsf((hm - THRc) * (1.f / THRc)));
            tr = TAUc * tr + zs;
            size_t o = ((size_t)t * B + b) * NH + tid;
            g_Z[o] = z; g_HT[o] = ht; g_TREC[o] = tr;
            zs = z;
        } else if (t > 0) {
            do_out(t - 1);
        }
        __syncthreads();

        unsigned m = 0;
        if (is_n) {
            zsh[tid] = z;
            m = __ballot_sync(0xffffffffu, z != 0.f);
            if (lane == 0) wcnt[w] = __popc(m);
        }
        __syncthreads();

        if (is_n) {
            int basew = 0, tot = 0;
#pragma unroll
            for (int c = 0; c < 16; c++) {
                int cc = wcnt[c];
                tot += cc;
                if (c < w) basew += cc;
            }
            nact = tot;
            if (z != 0.f)
                list[basew + __popc(m & ((1u << lane) - 1u))] = tid;
        }
        __syncthreads();
    }
    if (!is_n) do_out(T - 1);
    __syncthreads();

    if (tid < NO) {
        float ef = 0.f;
        for (int t = T - 1; t >= 0; t--) {
            ef = errh[t * NO + tid] + KAPc * ef;
            g_EF[((size_t)t * B + b) * NO + tid] = ef;
        }
    }
}

// ---------------- A[m,r] = (EF[m,:] . wout[:,r]) * HT[m,r] ----------------
__global__ void k_A(const float* __restrict__ wout) {
    int gid = blockIdx.x * 256 + threadIdx.x;
    if (gid >= T * B * NH) return;
    int m = gid >> 9;
    int r = gid & (NH - 1);
    const float* ef = g_EF + (size_t)m * NO;
    float L = 0.f;
#pragma unroll
    for (int o = 0; o < NO; o++) L += ef[o] * wout[o * NH + r];
    g_A[gid] = L * g_HT[gid];
}

// ---------------- small 64x64 A^T B for go ----------------
__global__ void k_gemmT64(const float* __restrict__ A, int sA,
                          const float* __restrict__ Bm, int sB,
                          float* __restrict__ Cp,
                          int M, int N, int K, int kchunk) {
    __shared__ float As[16][64];
    __shared__ float Bs[16][64];
    int m0 = blockIdx.y * 64, n0 = blockIdx.x * 64;
    int z = blockIdx.z;
    int k0s = z * kchunk;
    int k0e = min(K, k0s + kchunk);
    int tid = threadIdx.x;
    int tx = tid & 15, ty = tid >> 4;
    float acc[4][4] = {};
    for (int k0 = k0s; k0 < k0e; k0 += 16) {
#pragma unroll
        for (int rep = 0; rep < 4; rep++) {
            int e = tid + rep * 256;
            int mm = e & 63, kk = e >> 6;
            int mg = m0 + mm;
            As[kk][mm] = (mg < M) ? A[(size_t)(k0 + kk) * sA + mg] : 0.f;
            int ng = n0 + mm;
            Bs[kk][mm] = (ng < N) ? Bm[(size_t)(k0 + kk) * sB + ng] : 0.f;
        }
        __syncthreads();
#pragma unroll
        for (int k = 0; k < 16; k++) {
            float a[4], bb[4];
#pragma unroll
            for (int i = 0; i < 4; i++) a[i]  = As[k][ty * 4 + i];
#pragma unroll
            for (int j = 0; j < 4; j++) bb[j] = Bs[k][tx * 4 + j];
#pragma unroll
            for (int i = 0; i < 4; i++)
#pragma unroll
                for (int j = 0; j < 4; j++) acc[i][j] += a[i] * bb[j];
        }
        __syncthreads();
    }
    float* C = Cp + (size_t)z * M * N;
#pragma unroll
    for (int i = 0; i < 4; i++) {
        int m = m0 + ty * 4 + i;
        if (m < M) {
#pragma unroll
            for (int j = 0; j < 4; j++) {
                int n = n0 + tx * 4 + j;
                if (n < N) C[(size_t)m * N + n] = acc[i][j];
            }
        }
    }
}

__global__ void k_reduce(const float* __restrict__ Cp, float* __restrict__ out,
                         int MN, int KS, float scale) {
    int i = blockIdx.x * 256 + threadIdx.x;
    if (i >= MN) return;
    float s = 0.f;
    for (int z = 0; z < KS; z++) s += Cp[(size_t)z * MN + i];
    out[i] = scale * s;
}

// ---------------- launch ----------------
extern "C" void kernel_launch(void* const* d_in, const int* in_sizes, int n_in,
                              void* d_out, int out_size) {
    const float* x     = (const float*)d_in[0];
    const float* label = (const float*)d_in[1];
    const float* w1    = (const float*)d_in[3];
    const float* wrec  = (const float*)d_in[4];
    const float* wout  = (const float*)d_in[5];
    float* out = (float*)d_out;
    float* gf = out + B * T * NO;          // [NH, NI]
    float* gr = gf + NH * NI;              // [NH, NH]
    float* go = gr + NH * NH;              // [NO, NH]

    cudaFuncSetAttribute(k_forward, cudaFuncAttributeMaxDynamicSharedMemorySize, FWD_SMEM);

    float *pA, *pTIN, *pTREC, *pZ, *pEF, *pGP;
    cudaGetSymbolAddress((void**)&pA,    g_A);
    cudaGetSymbolAddress((void**)&pTIN,  g_TIN);
    cudaGetSymbolAddress((void**)&pTREC, g_TREC);
    cudaGetSymbolAddress((void**)&pZ,    g_Z);
    cudaGetSymbolAddress((void**)&pEF,   g_EF);
    cudaGetSymbolAddress((void**)&pGP,   g_gpart);

    k_tin<<<(B * NI + 255) / 256, 256>>>(x);
    k_gemmX<<<dim3(4, 50), 256>>>(x, w1);        // fp32 — precision-critical
    k_forward<<<B, 640, FWD_SMEM>>>(wrec, wout, label, out);
    k_A<<<(T * B * NH + 255) / 256, 256>>>(wout);

    // gf = LR * A^T @ TIN   [512 x 700], K=6400, splitK 8  (tf32 3x-split)
    k_mma<<<dim3(6, 4, 8), 256>>>(pA, NH, pTIN, NI, pGP, NH, NI, 800);
    k_reduce<<<(NH * NI + 255) / 256, 256>>>(pGP, gf, NH * NI, 8, LRc);

    // gr = LR * A^T @ TREC  [512 x 512], K=6400, splitK 8  (tf32 3x-split)
    k_mma<<<dim3(4, 4, 8), 256>>>(pA, NH, pTREC, NH, pGP, NH, NH, 800);
    k_reduce<<<(NH * NH + 255) / 256, 256>>>(pGP, gr, NH * NH, 8, LRc);

    // go = LR * EF^T @ Z    [20 x 512], K=6400, splitK 8
    k_gemmT64<<<dim3(8, 1, 8), 256>>>(pEF, NO, pZ, NH, pGP, NO, NH, T * B, 800);
    k_reduce<<<(NO * NH + 255) / 256, 256>>>(pGP, go, NO * NH, 8, LRc);
}

// round 9
// speedup vs baseline: 1.6686x; 1.6686x over previous
#include <cuda_runtime.h>

#define B   64
#define T   100
#define NI  700
#define NH  512
#define NO  20
#define TAUc 0.6f
#define KAPc 0.6f
#define THRc 0.6f
#define LRc  0.05f

// ---------------- persistent device scratch ----------------
__device__ float g_XP  [T*B*NH];   // x @ W1^T, rows m = t*B+b
__device__ float g_TIN [T*B*NI];
__device__ float g_TREC[T*B*NH];
__device__ float g_HT  [T*B*NH];
__device__ float g_Z   [T*B*NH];
__device__ float g_EF  [T*B*NO];
__device__ float g_A   [T*B*NH];
__device__ float g_gpart[8*512*700];

// forward smem layout (dynamic): ws[NO*NH] | zsh[NH] | errh[T*NO] | list[NH] | wcnt[16]
#define FWD_SMEM ((NO*NH + NH + T*NO + 16) * 4 + NH * 4)

// ---------------- tin scan (no recurrence) ----------------
__global__ void k_tin(const float* __restrict__ x) {
    int n = blockIdx.x * blockDim.x + threadIdx.x;
    if (n >= B * NI) return;
    int b = n / NI, i = n - b * NI;
    float tv = 0.f;
    for (int t = 0; t < T; t++) {
        tv = TAUc * tv + x[(b * T + t) * NI + i];
        g_TIN[((size_t)t * B + b) * NI + i] = tv;
    }
}

// ---------------- Xproj = X @ W1^T : [6400,512], K=700, fp32 SIMT ----------------
// PRECISION-CRITICAL: feeds the spike threshold. Staged values and FFMA order are
// bitwise-identical to the round-6 passing kernel; only load timing is pipelined.
__global__ __launch_bounds__(256, 2) void k_gemmX(const float* __restrict__ x,
                                                  const float* __restrict__ w1) {
    __shared__ float As[16][129];
    __shared__ float Bs[16][129];
    int m0 = blockIdx.y * 128, n0 = blockIdx.x * 128;
    int tid = threadIdx.x, tx = tid & 15, ty = tid >> 4;
    float acc[8][8] = {};

    float4 va[2], vb[2];

    auto ldtile = [&](int k0) {
#pragma unroll
        for (int rep = 0; rep < 2; rep++) {
            int f = tid + rep * 256;
            int mm = f >> 2, kq = f & 3;
            int kg = k0 + kq * 4;
            {
                int m = m0 + mm, t = m >> 6, b = m & 63;
                const float* xp = &x[((size_t)b * T + t) * NI + kg];
                float4 v;
                if (kg + 3 < NI) v = *(const float4*)xp;
                else {
                    v.x = (kg + 0 < NI) ? xp[0] : 0.f;
                    v.y = (kg + 1 < NI) ? xp[1] : 0.f;
                    v.z = (kg + 2 < NI) ? xp[2] : 0.f;
                    v.w = (kg + 3 < NI) ? xp[3] : 0.f;
                }
                va[rep] = v;
            }
            {
                int n = n0 + mm;
                const float* wp = &w1[(size_t)n * NI + kg];
                float4 v;
                if (kg + 3 < NI) v = *(const float4*)wp;
                else {
                    v.x = (kg + 0 < NI) ? wp[0] : 0.f;
                    v.y = (kg + 1 < NI) ? wp[1] : 0.f;
                    v.z = (kg + 2 < NI) ? wp[2] : 0.f;
                    v.w = (kg + 3 < NI) ? wp[3] : 0.f;
                }
                vb[rep] = v;
            }
        }
    };
    auto sttile = [&]() {
#pragma unroll
        for (int rep = 0; rep < 2; rep++) {
            int f = tid + rep * 256;
            int mm = f >> 2, kq = f & 3;
            As[kq * 4 + 0][mm] = va[rep].x; As[kq * 4 + 1][mm] = va[rep].y;
            As[kq * 4 + 2][mm] = va[rep].z; As[kq * 4 + 3][mm] = va[rep].w;
            Bs[kq * 4 + 0][mm] = vb[rep].x; Bs[kq * 4 + 1][mm] = vb[rep].y;
            Bs[kq * 4 + 2][mm] = vb[rep].z; Bs[kq * 4 + 3][mm] = vb[rep].w;
        }
    };

    ldtile(0);
    for (int k0 = 0; k0 < NI; k0 += 16) {
        sttile();
        __syncthreads();
        if (k0 + 16 < NI) ldtile(k0 + 16);   // LDGs overlap with compute below
#pragma unroll
        for (int k = 0; k < 16; k++) {
            float a[8], bb[8];
#pragma unroll
            for (int i = 0; i < 4; i++) {
                a[i]      = As[k][ty * 4 + i];
                a[4 + i]  = As[k][64 + ty * 4 + i];
                bb[i]     = Bs[k][tx * 4 + i];
                bb[4 + i] = Bs[k][64 + tx * 4 + i];
            }
#pragma unroll
            for (int i = 0; i < 8; i++)
#pragma unroll
                for (int j = 0; j < 8; j++) acc[i][j] += a[i] * bb[j];
        }
        __syncthreads();
    }
#pragma unroll
    for (int i = 0; i < 8; i++) {
        int m = m0 + ((i < 4) ? ty * 4 + i : 64 + ty * 4 + (i - 4));
#pragma unroll
        for (int j = 0; j < 8; j++) {
            int n = n0 + ((j < 4) ? tx * 4 + j : 64 + tx * 4 + (j - 4));
            g_XP[(size_t)m * NH + n] = acc[i][j];
        }
    }
}

// ---------------- forward: one block per sample, compacted spike list ----------------
// Gather is software-pipelined (load batch i+1 while summing batch i); FADD order
// identical to round 6 -> bitwise-identical spike trajectory.
__global__ __launch_bounds__(640) void k_forward(const float* __restrict__ wrec,
                                                 const float* __restrict__ wout,
                                                 const float* __restrict__ label,
                                                 float* __restrict__ out) {
    extern __shared__ float sm[];
    float* ws   = sm;                       // NO*NH
    float* zsh  = ws + NO * NH;             // NH
    float* errh = zsh + NH;                 // T*NO
    int*   list = (int*)(errh + T * NO);    // NH
    int*   wcnt = list + NH;                // 16

    int b = blockIdx.x;
    int tid = threadIdx.x, lane = tid & 31, w = tid >> 5;
    bool is_n = (tid < NH);
    int ow = w - 16;

    for (int i = tid; i < NO * NH; i += 640) ws[i] = wout[i];
    if (tid < NH) zsh[tid] = 0.f;
    if (tid < 16) wcnt[tid] = 0;
    __syncthreads();

    float hm = 0.f, tr = 0.f, zs = 0.f;
    float om[5] = {}, os[5] = {};
    int nact = 0;

    auto do_out = [&](int tp) {
#pragma unroll
        for (int q = 0; q < 5; q++) {
            int o = ow * 5 + q;
            float s = 0.f;
#pragma unroll
            for (int c = 0; c < 16; c++)
                s += zsh[c * 32 + lane] * ws[o * NH + c * 32 + lane];
#pragma unroll
            for (int off = 16; off; off >>= 1) s += __shfl_xor_sync(0xffffffffu, s, off);
            om[q] = TAUc * om[q] * (1.f - os[q]) + s;
            os[q] = (om[q] >= THRc) ? 1.f : 0.f;
            if (lane == 0) {
                out[((size_t)b * T + tp) * NO + o] = os[q];
                errh[tp * NO + o] = os[q] - label[((size_t)b * T + tp) * NO + o];
            }
        }
    };

    for (int t = 0; t < T; t++) {
        float z = 0.f, ht = 0.f;
        if (is_n) {
            float xp = __ldg(&g_XP[((size_t)t * B + b) * NH + tid]);
            float acc = 0.f;
            if (nact > 0) {
                float v0[16], v1[16];
#pragma unroll
                for (int u = 0; u < 16; u++)
                    v0[u] = (u < nact) ? __ldg(&wrec[(size_t)list[u] * NH + tid]) : 0.f;
                for (int i = 16; i < nact; i += 16) {
#pragma unroll
                    for (int u = 0; u < 16; u++) {
                        int ix = i + u;
                        v1[u] = (ix < nact) ? __ldg(&wrec[(size_t)list[ix] * NH + tid]) : 0.f;
                    }
#pragma unroll
                    for (int u = 0; u < 16; u++) acc += v0[u];
#pragma unroll
                    for (int u = 0; u < 16; u++) v0[u] = v1[u];
                }
#pragma unroll
                for (int u = 0; u < 16; u++) acc += v0[u];
            }
            hm = TAUc * hm * (1.f - zs) + xp + acc;
            z  = (hm >= THRc) ? 1.f : 0.f;
            ht = TAUc * fmaxf(0.f, 1.f - fabsf((hm - THRc) * (1.f / THRc)));
            tr = TAUc * tr + zs;
            size_t o = ((size_t)t * B + b) * NH + tid;
            g_Z[o] = z; g_HT[o] = ht; g_TREC[o] = tr;
            zs = z;
        } else if (t > 0) {
            do_out(t - 1);
        }
        __syncthreads();

        unsigned m = 0;
        if (is_n) {
            zsh[tid] = z;
            m = __ballot_sync(0xffffffffu, z != 0.f);
            if (lane == 0) wcnt[w] = __popc(m);
        }
        __syncthreads();

        if (is_n) {
            int basew = 0, tot = 0;
#pragma unroll
            for (int c = 0; c < 16; c++) {
                int cc = wcnt[c];
                tot += cc;
                if (c < w) basew += cc;
            }
            nact = tot;
            if (z != 0.f)
                list[basew + __popc(m & ((1u << lane) - 1u))] = tid;
        }
        __syncthreads();
    }
    if (!is_n) do_out(T - 1);
    __syncthreads();

    if (tid < NO) {
        float ef = 0.f;
        for (int t = T - 1; t >= 0; t--) {
            ef = errh[t * NO + tid] + KAPc * ef;
            g_EF[((size_t)t * B + b) * NO + tid] = ef;
        }
    }
}

// ---------------- A[m,r] = (EF[m,:] . wout[:,r]) * HT[m,r] ----------------
__global__ void k_A(const float* __restrict__ wout) {
    int gid = blockIdx.x * 256 + threadIdx.x;
    if (gid >= T * B * NH) return;
    int m = gid >> 9;
    int r = gid & (NH - 1);
    const float* ef = g_EF + (size_t)m * NO;
    float L = 0.f;
#pragma unroll
    for (int o = 0; o < NO; o++) L += ef[o] * wout[o * NH + r];
    g_A[gid] = L * g_HT[gid];
}

// ---------------- C = A^T B, 128x128 tiles, split-K, reg-prefetch pipelined ----------------
__global__ __launch_bounds__(256, 2) void k_gemm128T(const float* __restrict__ A, int sA,
                                                     const float* __restrict__ Bm, int sB,
                                                     float* __restrict__ Cp,
                                                     int M, int N, int kchunk) {
    __shared__ float As[16][128];
    __shared__ float Bs[16][128];
    int n0 = blockIdx.x * 128, m0 = blockIdx.y * 128;
    int z = blockIdx.z;
    int k0s = z * kchunk;
    int k0e = k0s + kchunk;
    int tid = threadIdx.x, tx = tid & 15, ty = tid >> 4;
    float acc[8][8] = {};

    float4 va[2], vb[2];

    auto ldtile = [&](int k0) {
#pragma unroll
        for (int rep = 0; rep < 2; rep++) {
            int f = tid + rep * 256;
            int kk = f >> 5, c4 = (f & 31) * 4;
            va[rep] = *(const float4*)&A[(size_t)(k0 + kk) * sA + m0 + c4];
            int n = n0 + c4;
            const float* bp = &Bm[(size_t)(k0 + kk) * sB + n];
            float4 bv;
            if (n + 3 < N) bv = *(const float4*)bp;
            else {
                bv.x = (n + 0 < N) ? bp[0] : 0.f;
                bv.y = (n + 1 < N) ? bp[1] : 0.f;
                bv.z = (n + 2 < N) ? bp[2] : 0.f;
                bv.w = (n + 3 < N) ? bp[3] : 0.f;
            }
            vb[rep] = bv;
        }
    };
    auto sttile = [&]() {
#pragma unroll
        for (int rep = 0; rep < 2; rep++) {
            int f = tid + rep * 256;
            int kk = f >> 5, c4 = (f & 31) * 4;
            *(float4*)&As[kk][c4] = va[rep];
            *(float4*)&Bs[kk][c4] = vb[rep];
        }
    };

    ldtile(k0s);
    for (int k0 = k0s; k0 < k0e; k0 += 16) {
        sttile();
        __syncthreads();
        if (k0 + 16 < k0e) ldtile(k0 + 16);  // overlap with compute
#pragma unroll
        for (int k = 0; k < 16; k++) {
            float a[8], bb[8];
            *(float4*)&a[0]  = *(float4*)&As[k][ty * 4];
            *(float4*)&a[4]  = *(float4*)&As[k][64 + ty * 4];
            *(float4*)&bb[0] = *(float4*)&Bs[k][tx * 4];
            *(float4*)&bb[4] = *(float4*)&Bs[k][64 + tx * 4];
#pragma unroll
            for (int i = 0; i < 8; i++)
#pragma unroll
                for (int j = 0; j < 8; j++) acc[i][j] += a[i] * bb[j];
        }
        __syncthreads();
    }
    float* C = Cp + (size_t)z * M * N;
#pragma unroll
    for (int i = 0; i < 8; i++) {
        int m = m0 + ((i < 4) ? ty * 4 + i : 64 + ty * 4 + (i - 4));
#pragma unroll
        for (int j = 0; j < 8; j++) {
            int n = n0 + ((j < 4) ? tx * 4 + j : 64 + tx * 4 + (j - 4));
            if (n < N) C[(size_t)m * N + n] = acc[i][j];
        }
    }
}

// ---------------- small 64x64 A^T B for go ----------------
__global__ void k_gemmT64(const float* __restrict__ A, int sA,
                          const float* __restrict__ Bm, int sB,
                          float* __restrict__ Cp,
                          int M, int N, int K, int kchunk) {
    __shared__ float As[16][64];
    __shared__ float Bs[16][64];
    int m0 = blockIdx.y * 64, n0 = blockIdx.x * 64;
    int z = blockIdx.z;
    int k0s = z * kchunk;
    int k0e = min(K, k0s + kchunk);
    int tid = threadIdx.x;
    int tx = tid & 15, ty = tid >> 4;
    float acc[4][4] = {};
    for (int k0 = k0s; k0 < k0e; k0 += 16) {
#pragma unroll
        for (int rep = 0; rep < 4; rep++) {
            int e = tid + rep * 256;
            int mm = e & 63, kk = e >> 6;
            int mg = m0 + mm;
            As[kk][mm] = (mg < M) ? A[(size_t)(k0 + kk) * sA + mg] : 0.f;
            int ng = n0 + mm;
            Bs[kk][mm] = (ng < N) ? Bm[(size_t)(k0 + kk) * sB + ng] : 0.f;
        }
        __syncthreads();
#pragma unroll
        for (int k = 0; k < 16; k++) {
            float a[4], bb[4];
#pragma unroll
            for (int i = 0; i < 4; i++) a[i]  = As[k][ty * 4 + i];
#pragma unroll
            for (int j = 0; j < 4; j++) bb[j] = Bs[k][tx * 4 + j];
#pragma unroll
            for (int i = 0; i < 4; i++)
#pragma unroll
                for (int j = 0; j < 4; j++) acc[i][j] += a[i] * bb[j];
        }
        __syncthreads();
    }
    float* C = Cp + (size_t)z * M * N;
#pragma unroll
    for (int i = 0; i < 4; i++) {
        int m = m0 + ty * 4 + i;
        if (m < M) {
#pragma unroll
            for (int j = 0; j < 4; j++) {
                int n = n0 + tx * 4 + j;
                if (n < N) C[(size_t)m * N + n] = acc[i][j];
            }
        }
    }
}

__global__ void k_reduce(const float* __restrict__ Cp, float* __restrict__ out,
                         int MN, int KS, float scale) {
    int i = blockIdx.x * 256 + threadIdx.x;
    if (i >= MN) return;
    float s = 0.f;
    for (int z = 0; z < KS; z++) s += Cp[(size_t)z * MN + i];
    out[i] = scale * s;
}

// ---------------- launch ----------------
extern "C" void kernel_launch(void* const* d_in, const int* in_sizes, int n_in,
                              void* d_out, int out_size) {
    const float* x     = (const float*)d_in[0];
    const float* label = (const float*)d_in[1];
    const float* w1    = (const float*)d_in[3];
    const float* wrec  = (const float*)d_in[4];
    const float* wout  = (const float*)d_in[5];
    float* out = (float*)d_out;
    float* gf = out + B * T * NO;          // [NH, NI]
    float* gr = gf + NH * NI;              // [NH, NH]
    float* go = gr + NH * NH;              // [NO, NH]

    cudaFuncSetAttribute(k_forward, cudaFuncAttributeMaxDynamicSharedMemorySize, FWD_SMEM);

    float *pA, *pTIN, *pTREC, *pZ, *pEF, *pGP;
    cudaGetSymbolAddress((void**)&pA,    g_A);
    cudaGetSymbolAddress((void**)&pTIN,  g_TIN);
    cudaGetSymbolAddress((void**)&pTREC, g_TREC);
    cudaGetSymbolAddress((void**)&pZ,    g_Z);
    cudaGetSymbolAddress((void**)&pEF,   g_EF);
    cudaGetSymbolAddress((void**)&pGP,   g_gpart);

    k_tin<<<(B * NI + 255) / 256, 256>>>(x);
    k_gemmX<<<dim3(4, 50), 256>>>(x, w1);        // fp32 — precision-critical
    k_forward<<<B, 640, FWD_SMEM>>>(wrec, wout, label, out);
    k_A<<<(T * B * NH + 255) / 256, 256>>>(wout);

    // gf = LR * A^T @ TIN   [512 x 700], K=6400, splitK 8
    k_gemm128T<<<dim3(6, 4, 8), 256>>>(pA, NH, pTIN, NI, pGP, NH, NI, 800);
    k_reduce<<<(NH * NI + 255) / 256, 256>>>(pGP, gf, NH * NI, 8, LRc);

    // gr = LR * A^T @ TREC  [512 x 512], K=6400, splitK 8
    k_gemm128T<<<dim3(4, 4, 8), 256>>>(pA, NH, pTREC, NH, pGP, NH, NH, 800);
    k_reduce<<<(NH * NH + 255) / 256, 256>>>(pGP, gr, NH * NH, 8, LRc);

    // go = LR * EF^T @ Z    [20 x 512], K=6400, splitK 8
    k_gemmT64<<<dim3(8, 1, 8), 256>>>(pEF, NO, pZ, NH, pGP, NO, NH, T * B, 800);
    k_reduce<<<(NO * NH + 255) / 256, 256>>>(pGP, go, NO * NH, 8, LRc);
}

// round 11
// speedup vs baseline: 1.7520x; 1.0500x over previous
#include <cuda_runtime.h>

#define B   64
#define T   100
#define NI  700
#define NH  512
#define NO  20
#define TAUc 0.6f
#define KAPc 0.6f
#define THRc 0.6f
#define LRc  0.05f

// ---------------- persistent device scratch ----------------
__device__ float g_XP  [T*B*NH];   // x @ W1^T, rows m = t*B+b
__device__ float g_TIN [T*B*NI];
__device__ float g_TREC[T*B*NH];
__device__ float g_HT  [T*B*NH];
__device__ float g_Z   [T*B*NH];
__device__ float g_S   [T*B*NO];   // Z @ wout^T
__device__ float g_EF  [T*B*NO];
__device__ float g_A   [T*B*NH];
__device__ float g_gpart[8*512*700];

// ---------------- tin scan (no recurrence) ----------------
__global__ void k_tin(const float* __restrict__ x) {
    int n = blockIdx.x * blockDim.x + threadIdx.x;
    if (n >= B * NI) return;
    int b = n / NI, i = n - b * NI;
    float tv = 0.f;
    for (int t = 0; t < T; t++) {
        tv = TAUc * tv + x[(b * T + t) * NI + i];
        g_TIN[((size_t)t * B + b) * NI + i] = tv;
    }
}

// ---------------- Xproj = X @ W1^T : [6400,512], K=700, fp32 SIMT ----------------
// PRECISION-CRITICAL: feeds the spike threshold. FFMA order identical to passing rounds.
__global__ __launch_bounds__(256, 2) void k_gemmX(const float* __restrict__ x,
                                                  const float* __restrict__ w1) {
    __shared__ float As[16][129];
    __shared__ float Bs[16][129];
    int m0 = blockIdx.y * 128, n0 = blockIdx.x * 128;
    int tid = threadIdx.x, tx = tid & 15, ty = tid >> 4;
    float acc[8][8] = {};

    float4 va[2], vb[2];

    auto ldtile = [&](int k0) {
#pragma unroll
        for (int rep = 0; rep < 2; rep++) {
            int f = tid + rep * 256;
            int mm = f >> 2, kq = f & 3;
            int kg = k0 + kq * 4;
            {
                int m = m0 + mm, t = m >> 6, b = m & 63;
                const float* xp = &x[((size_t)b * T + t) * NI + kg];
                float4 v;
                if (kg + 3 < NI) v = *(const float4*)xp;
                else {
                    v.x = (kg + 0 < NI) ? xp[0] : 0.f;
                    v.y = (kg + 1 < NI) ? xp[1] : 0.f;
                    v.z = (kg + 2 < NI) ? xp[2] : 0.f;
                    v.w = (kg + 3 < NI) ? xp[3] : 0.f;
                }
                va[rep] = v;
            }
            {
                int n = n0 + mm;
                const float* wp = &w1[(size_t)n * NI + kg];
                float4 v;
                if (kg + 3 < NI) v = *(const float4*)wp;
                else {
                    v.x = (kg + 0 < NI) ? wp[0] : 0.f;
                    v.y = (kg + 1 < NI) ? wp[1] : 0.f;
                    v.z = (kg + 2 < NI) ? wp[2] : 0.f;
                    v.w = (kg + 3 < NI) ? wp[3] : 0.f;
                }
                vb[rep] = v;
            }
        }
    };
    auto sttile = [&]() {
#pragma unroll
        for (int rep = 0; rep < 2; rep++) {
            int f = tid + rep * 256;
            int mm = f >> 2, kq = f & 3;
            As[kq * 4 + 0][mm] = va[rep].x; As[kq * 4 + 1][mm] = va[rep].y;
            As[kq * 4 + 2][mm] = va[rep].z; As[kq * 4 + 3][mm] = va[rep].w;
            Bs[kq * 4 + 0][mm] = vb[rep].x; Bs[kq * 4 + 1][mm] = vb[rep].y;
            Bs[kq * 4 + 2][mm] = vb[rep].z; Bs[kq * 4 + 3][mm] = vb[rep].w;
        }
    };

    ldtile(0);
    for (int k0 = 0; k0 < NI; k0 += 16) {
        sttile();
        __syncthreads();
        if (k0 + 16 < NI) ldtile(k0 + 16);
#pragma unroll
        for (int k = 0; k < 16; k++) {
            float a[8], bb[8];
#pragma unroll
            for (int i = 0; i < 4; i++) {
                a[i]      = As[k][ty * 4 + i];
                a[4 + i]  = As[k][64 + ty * 4 + i];
                bb[i]     = Bs[k][tx * 4 + i];
                bb[4 + i] = Bs[k][64 + tx * 4 + i];
            }
#pragma unroll
            for (int i = 0; i < 8; i++)
#pragma unroll
                for (int j = 0; j < 8; j++) acc[i][j] += a[i] * bb[j];
        }
        __syncthreads();
    }
#pragma unroll
    for (int i = 0; i < 8; i++) {
        int m = m0 + ((i < 4) ? ty * 4 + i : 64 + ty * 4 + (i - 4));
#pragma unroll
        for (int j = 0; j < 8; j++) {
            int n = n0 + ((j < 4) ? tx * 4 + j : 64 + tx * 4 + (j - 4));
            g_XP[(size_t)m * NH + n] = acc[i][j];
        }
    }
}

// ---------------- forward: 128 threads/sample, float4 gather, dual-window pipeline ----------------
// Thread q owns neurons 4q..4q+3 (state in float4 regs). Active rows gathered as
// LDG.128 (4x fewer LSU ops). Per-neuron add order = ascending row index -> bitwise
// identical spike trajectory to all passing rounds.
__global__ __launch_bounds__(128) void k_forward(const float* __restrict__ wrec) {
    __shared__ int list[NH + 64];      // +64 pad: predicated-off window reads may index past nact
    __shared__ unsigned zmask[16];
    int b = blockIdx.x;
    int q = threadIdx.x;               // 0..127
    int lane = q & 31, w = q >> 5;

    const float4* wrec4 = (const float4*)wrec;
    float4 hm = {0,0,0,0}, tr = {0,0,0,0}, zs = {0,0,0,0};
    int nact = 0;

    for (int t = 0; t < T; t++) {
        float4 xp = __ldg((const float4*)&g_XP[((size_t)t * B + b) * NH] + q);
        float4 acc = {0,0,0,0};
        if (nact > 0) {
            float4 v0[16], v1[16];
            auto ldwin = [&](int k, float4* v) {
#pragma unroll
                for (int u = 0; u < 16; u++) {
                    int ix = k * 16 + u;
                    float4 zz = {0.f, 0.f, 0.f, 0.f};
                    v[u] = (ix < nact) ? __ldg(&wrec4[(size_t)list[ix] * 128 + q]) : zz;
                }
            };
            auto sumwin = [&](const float4* v) {
#pragma unroll
                for (int u = 0; u < 16; u++) {
                    acc.x += v[u].x; acc.y += v[u].y; acc.z += v[u].z; acc.w += v[u].w;
                }
            };
            int npairs = (nact + 31) >> 5;
            ldwin(0, v0);
            for (int p = 0; p < npairs; p++) {
                ldwin(2 * p + 1, v1);
                sumwin(v0);                // rows 32p .. 32p+15 (ascending)
                ldwin(2 * p + 2, v0);
                sumwin(v1);                // rows 32p+16 .. 32p+31 (padding adds 0 = bit-neutral)
            }
        }
        // LIF update (same expression text as passing rounds, componentwise)
        float4 z, ht;
        hm.x = TAUc * hm.x * (1.f - zs.x) + xp.x + acc.x;
        hm.y = TAUc * hm.y * (1.f - zs.y) + xp.y + acc.y;
        hm.z = TAUc * hm.z * (1.f - zs.z) + xp.z + acc.z;
        hm.w = TAUc * hm.w * (1.f - zs.w) + xp.w + acc.w;
        z.x = (hm.x >= THRc) ? 1.f : 0.f;
        z.y = (hm.y >= THRc) ? 1.f : 0.f;
        z.z = (hm.z >= THRc) ? 1.f : 0.f;
        z.w = (hm.w >= THRc) ? 1.f : 0.f;
        ht.x = TAUc * fmaxf(0.f, 1.f - fabsf((hm.x - THRc) * (1.f / THRc)));
        ht.y = TAUc * fmaxf(0.f, 1.f - fabsf((hm.y - THRc) * (1.f / THRc)));
        ht.z = TAUc * fmaxf(0.f, 1.f - fabsf((hm.z - THRc) * (1.f / THRc)));
        ht.w = TAUc * fmaxf(0.f, 1.f - fabsf((hm.w - THRc) * (1.f / THRc)));
        tr.x = TAUc * tr.x + zs.x;
        tr.y = TAUc * tr.y + zs.y;
        tr.z = TAUc * tr.z + zs.z;
        tr.w = TAUc * tr.w + zs.w;
        size_t o4 = ((size_t)t * B + b) * 128 + q;
        ((float4*)g_Z)[o4] = z; ((float4*)g_HT)[o4] = ht; ((float4*)g_TREC)[o4] = tr;
        zs = z;

        // build 32-neuron spike masks via shfl-OR of 4-bit nibbles
        unsigned nib = (z.x != 0.f ? 1u : 0u) | (z.y != 0.f ? 2u : 0u)
                     | (z.z != 0.f ? 4u : 0u) | (z.w != 0.f ? 8u : 0u);
        unsigned word = nib << ((lane & 7) * 4);
        word |= __shfl_xor_sync(0xffffffffu, word, 1);
        word |= __shfl_xor_sync(0xffffffffu, word, 2);
        word |= __shfl_xor_sync(0xffffffffu, word, 4);
        if ((lane & 7) == 0) zmask[w * 4 + (lane >> 3)] = word;
        __syncthreads();                 // gather done (list free) + zmask ready

        int tot = 0, pre = 0;
        int myc = q >> 3;
#pragma unroll
        for (int c = 0; c < 16; c++) {
            int pc = __popc(zmask[c]);
            if (c < myc) pre += pc;
            tot += pc;
        }
        pre += __popc(zmask[myc] & ((1u << ((q & 7) * 4)) - 1u));
        nact = tot;
        if (nib & 1u) list[pre++] = 4 * q + 0;
        if (nib & 2u) list[pre++] = 4 * q + 1;
        if (nib & 4u) list[pre++] = 4 * q + 2;
        if (nib & 8u) list[pre++] = 4 * q + 3;
        __syncthreads();                 // list ready for next step
    }
}

// ---------------- S[m,o] = Z[m,:] . wout[o,:] ----------------
__global__ __launch_bounds__(256) void k_s(const float* __restrict__ wout) {
    __shared__ float ws[NO * NH];
    int m0 = blockIdx.x * 64;
    int tid = threadIdx.x, w = tid >> 5, lane = tid & 31;
    for (int i = tid; i < NO * NH; i += 256) ws[i] = wout[i];
    __syncthreads();
#pragma unroll 1
    for (int r = 0; r < 8; r++) {
        int m = m0 + w * 8 + r;
        float zv[16];
#pragma unroll
        for (int c = 0; c < 16; c++) zv[c] = g_Z[(size_t)m * NH + c * 32 + lane];
#pragma unroll 1
        for (int o = 0; o < NO; o++) {
            float s = 0.f;
#pragma unroll
            for (int c = 0; c < 16; c++) s += zv[c] * ws[o * NH + c * 32 + lane];
#pragma unroll
            for (int off = 16; off; off >>= 1) s += __shfl_xor_sync(0xffffffffu, s, off);
            if (lane == 0) g_S[(size_t)m * NO + o] = s;
        }
    }
}

// ---------------- output LIF scan + reverse kappa filter ----------------
__global__ void k_scan(const float* __restrict__ label, float* __restrict__ out) {
    int n = blockIdx.x * 256 + threadIdx.x;
    if (n >= B * NO) return;
    int b = n / NO, o = n - b * NO;
    float om = 0.f, os = 0.f;
    for (int t = 0; t < T; t += 4) {
        float sv[4], lv[4];
#pragma unroll
        for (int u = 0; u < 4; u++) {
            sv[u] = g_S[((size_t)(t + u) * B + b) * NO + o];
            lv[u] = label[((size_t)b * T + t + u) * NO + o];
        }
#pragma unroll
        for (int u = 0; u < 4; u++) {
            om = TAUc * om * (1.f - os) + sv[u];
            os = (om >= THRc) ? 1.f : 0.f;
            out[((size_t)b * T + t + u) * NO + o] = os;
            g_EF[((size_t)(t + u) * B + b) * NO + o] = os - lv[u];
        }
    }
    float ef = 0.f;
    for (int t = T - 4; t >= 0; t -= 4) {
        float ev[4];
#pragma unroll
        for (int u = 0; u < 4; u++) ev[u] = g_EF[((size_t)(t + u) * B + b) * NO + o];
#pragma unroll
        for (int u = 3; u >= 0; u--) {
            ef = ev[u] + KAPc * ef;
            g_EF[((size_t)(t + u) * B + b) * NO + o] = ef;
        }
    }
}

// ---------------- A[m,r] = (EF[m,:] . wout[:,r]) * HT[m,r] ----------------
__global__ void k_A(const float* __restrict__ wout) {
    int gid = blockIdx.x * 256 + threadIdx.x;
    if (gid >= T * B * NH) return;
    int m = gid >> 9;
    int r = gid & (NH - 1);
    const float* ef = g_EF + (size_t)m * NO;
    float L = 0.f;
#pragma unroll
    for (int o = 0; o < NO; o++) L += ef[o] * wout[o * NH + r];
    g_A[gid] = L * g_HT[gid];
}

// ---------------- C = A^T B, 128x128 tiles, split-K, reg-prefetch pipelined ----------------
__global__ __launch_bounds__(256, 2) void k_gemm128T(const float* __restrict__ A, int sA,
                                                     const float* __restrict__ Bm, int sB,
                                                     float* __restrict__ Cp,
                                                     int M, int N, int kchunk) {
    __shared__ float As[16][128];
    __shared__ float Bs[16][128];
    int n0 = blockIdx.x * 128, m0 = blockIdx.y * 128;
    int z = blockIdx.z;
    int k0s = z * kchunk;
    int k0e = k0s + kchunk;
    int tid = threadIdx.x, tx = tid & 15, ty = tid >> 4;
    float acc[8][8] = {};

    float4 va[2], vb[2];

    auto ldtile = [&](int k0) {
#pragma unroll
        for (int rep = 0; rep < 2; rep++) {
            int f = tid + rep * 256;
            int kk = f >> 5, c4 = (f & 31) * 4;
            va[rep] = *(const float4*)&A[(size_t)(k0 + kk) * sA + m0 + c4];
            int n = n0 + c4;
            const float* bp = &Bm[(size_t)(k0 + kk) * sB + n];
            float4 bv;
            if (n + 3 < N) bv = *(const float4*)bp;
            else {
                bv.x = (n + 0 < N) ? bp[0] : 0.f;
                bv.y = (n + 1 < N) ? bp[1] : 0.f;
                bv.z = (n + 2 < N) ? bp[2] : 0.f;
                bv.w = (n + 3 < N) ? bp[3] : 0.f;
            }
            vb[rep] = bv;
        }
    };
    auto sttile = [&]() {
#pragma unroll
        for (int rep = 0; rep < 2; rep++) {
            int f = tid + rep * 256;
            int kk = f >> 5, c4 = (f & 31) * 4;
            *(float4*)&As[kk][c4] = va[rep];
            *(float4*)&Bs[kk][c4] = vb[rep];
        }
    };

    ldtile(k0s);
    for (int k0 = k0s; k0 < k0e; k0 += 16) {
        sttile();
        __syncthreads();
        if (k0 + 16 < k0e) ldtile(k0 + 16);
#pragma unroll
        for (int k = 0; k < 16; k++) {
            float a[8], bb[8];
            *(float4*)&a[0]  = *(float4*)&As[k][ty * 4];
            *(float4*)&a[4]  = *(float4*)&As[k][64 + ty * 4];
            *(float4*)&bb[0] = *(float4*)&Bs[k][tx * 4];
            *(float4*)&bb[4] = *(float4*)&Bs[k][64 + tx * 4];
#pragma unroll
            for (int i = 0; i < 8; i++)
#pragma unroll
                for (int j = 0; j < 8; j++) acc[i][j] += a[i] * bb[j];
        }
        __syncthreads();
    }
    float* C = Cp + (size_t)z * M * N;
#pragma unroll
    for (int i = 0; i < 8; i++) {
        int m = m0 + ((i < 4) ? ty * 4 + i : 64 + ty * 4 + (i - 4));
#pragma unroll
        for (int j = 0; j < 8; j++) {
            int n = n0 + ((j < 4) ? tx * 4 + j : 64 + tx * 4 + (j - 4));
            if (n < N) C[(size_t)m * N + n] = acc[i][j];
        }
    }
}

// ---------------- small 64x64 A^T B for go ----------------
__global__ void k_gemmT64(const float* __restrict__ A, int sA,
                          const float* __restrict__ Bm, int sB,
                          float* __restrict__ Cp,
                          int M, int N, int K, int kchunk) {
    __shared__ float As[16][64];
    __shared__ float Bs[16][64];
    int m0 = blockIdx.y * 64, n0 = blockIdx.x * 64;
    int z = blockIdx.z;
    int k0s = z * kchunk;
    int k0e = min(K, k0s + kchunk);
    int tid = threadIdx.x;
    int tx = tid & 15, ty = tid >> 4;
    float acc[4][4] = {};
    for (int k0 = k0s; k0 < k0e; k0 += 16) {
#pragma unroll
        for (int rep = 0; rep < 4; rep++) {
            int e = tid + rep * 256;
            int mm = e & 63, kk = e >> 6;
            int mg = m0 + mm;
            As[kk][mm] = (mg < M) ? A[(size_t)(k0 + kk) * sA + mg] : 0.f;
            int ng = n0 + mm;
            Bs[kk][mm] = (ng < N) ? Bm[(size_t)(k0 + kk) * sB + ng] : 0.f;
        }
        __syncthreads();
#pragma unroll
        for (int k = 0; k < 16; k++) {
            float a[4], bb[4];
#pragma unroll
            for (int i = 0; i < 4; i++) a[i]  = As[k][ty * 4 + i];
#pragma unroll
            for (int j = 0; j < 4; j++) bb[j] = Bs[k][tx * 4 + j];
#pragma unroll
            for (int i = 0; i < 4; i++)
#pragma unroll
                for (int j = 0; j < 4; j++) acc[i][j] += a[i] * bb[j];
        }
        __syncthreads();
    }
    float* C = Cp + (size_t)z * M * N;
#pragma unroll
    for (int i = 0; i < 4; i++) {
        int m = m0 + ty * 4 + i;
        if (m < M) {
#pragma unroll
            for (int j = 0; j < 4; j++) {
                int n = n0 + tx * 4 + j;
                if (n < N) C[(size_t)m * N + n] = acc[i][j];
            }
        }
    }
}

__global__ void k_reduce(const float* __restrict__ Cp, float* __restrict__ out,
                         int MN, int KS, float scale) {
    int i = blockIdx.x * 256 + threadIdx.x;
    if (i >= MN) return;
    float s = 0.f;
    for (int z = 0; z < KS; z++) s += Cp[(size_t)z * MN + i];
    out[i] = scale * s;
}

// ---------------- launch ----------------
extern "C" void kernel_launch(void* const* d_in, const int* in_sizes, int n_in,
                              void* d_out, int out_size) {
    const float* x     = (const float*)d_in[0];
    const float* label = (const float*)d_in[1];
    const float* w1    = (const float*)d_in[3];
    const float* wrec  = (const float*)d_in[4];
    const float* wout  = (const float*)d_in[5];
    float* out = (float*)d_out;
    float* gf = out + B * T * NO;          // [NH, NI]
    float* gr = gf + NH * NI;              // [NH, NH]
    float* go = gr + NH * NH;              // [NO, NH]

    float *pA, *pTIN, *pTREC, *pZ, *pEF, *pGP;
    cudaGetSymbolAddress((void**)&pA,    g_A);
    cudaGetSymbolAddress((void**)&pTIN,  g_TIN);
    cudaGetSymbolAddress((void**)&pTREC, g_TREC);
    cudaGetSymbolAddress((void**)&pZ,    g_Z);
    cudaGetSymbolAddress((void**)&pEF,   g_EF);
    cudaGetSymbolAddress((void**)&pGP,   g_gpart);

    k_tin<<<(B * NI + 255) / 256, 256>>>(x);
    k_gemmX<<<dim3(4, 50), 256>>>(x, w1);        // fp32 — precision-critical
    k_forward<<<B, 128>>>(wrec);
    k_s<<<100, 256>>>(wout);
    k_scan<<<5, 256>>>(label, out);
    k_A<<<(T * B * NH + 255) / 256, 256>>>(wout);

    // gf = LR * A^T @ TIN   [512 x 700], K=6400, splitK 8
    k_gemm128T<<<dim3(6, 4, 8), 256>>>(pA, NH, pTIN, NI, pGP, NH, NI, 800);
    k_reduce<<<(NH * NI + 255) / 256, 256>>>(pGP, gf, NH * NI, 8, LRc);

    // gr = LR * A^T @ TREC  [512 x 512], K=6400, splitK 8
    k_gemm128T<<<dim3(4, 4, 8), 256>>>(pA, NH, pTREC, NH, pGP, NH, NH, 800);
    k_reduce<<<(NH * NH + 255) / 256, 256>>>(pGP, gr, NH * NH, 8, LRc);

    // go = LR * EF^T @ Z    [20 x 512], K=6400, splitK 8
    k_gemmT64<<<dim3(8, 1, 8), 256>>>(pEF, NO, pZ, NH, pGP, NO, NH, T * B, 800);
    k_reduce<<<(NO * NH + 255) / 256, 256>>>(pGP, go, NO * NH, 8, LRc);
}

// round 12
// speedup vs baseline: 1.9499x; 1.1130x over previous
#include <cuda_runtime.h>

#define B   64
#define T   100
#define NI  700
#define NH  512
#define NO  20
#define TAUc 0.6f
#define KAPc 0.6f
#define THRc 0.6f
#define LRc  0.05f

// ---------------- persistent device scratch ----------------
__device__ float g_XP  [T*B*NH];   // x @ W1^T, rows m = t*B+b
__device__ float g_TIN [T*B*NI];
__device__ float g_TREC[T*B*NH];
__device__ float g_HT  [T*B*NH];
__device__ float g_Z   [T*B*NH];
__device__ float g_S   [T*B*NO];   // Z @ wout^T
__device__ float g_EF  [T*B*NO];
__device__ float g_A   [T*B*NH];

// gradient split-K partials: gf 7 parts, gr 8 parts, go 8 parts
#define GF_MN (NH*NI)              // 358400
#define GR_MN (NH*NH)              // 262144
#define GO_MN (NO*NH)              // 10240
#define GFP_OFF 0
#define GRP_OFF (7*GF_MN)          // 2508800
#define GOP_OFF (GRP_OFF + 8*GR_MN)
__device__ float g_gp[GOP_OFF + 8*GO_MN];

// ---------------- fused head: gemmX blocks [0,200) + tin blocks [200,375) ----------------
// gemmX: Xproj = X @ W1^T [6400,512] K=700. PRECISION-CRITICAL: body + tile mapping
// bitwise-identical to passing rounds. tin: forward tau-scan of x (independent).
__global__ __launch_bounds__(256, 2) void k_head(const float* __restrict__ x,
                                                 const float* __restrict__ w1) {
    __shared__ float As[16][129];
    __shared__ float Bs[16][129];
    int bid = blockIdx.x;
    int tid = threadIdx.x;

    if (bid >= 200) {               // ---- tin path ----
        int n = (bid - 200) * 256 + tid;
        if (n < B * NI) {
            int b = n / NI, i = n - b * NI;
            float tv = 0.f;
            for (int t = 0; t < T; t++) {
                tv = TAUc * tv + x[(b * T + t) * NI + i];
                g_TIN[((size_t)t * B + b) * NI + i] = tv;
            }
        }
        return;
    }

    // ---- gemmX path (mapping: n0 = (bid&3)*128, m0 = (bid>>2)*128) ----
    int m0 = (bid >> 2) * 128, n0 = (bid & 3) * 128;
    int tx = tid & 15, ty = tid >> 4;
    float acc[8][8] = {};
    float4 va[2], vb[2];

    auto ldtile = [&](int k0) {
#pragma unroll
        for (int rep = 0; rep < 2; rep++) {
            int f = tid + rep * 256;
            int mm = f >> 2, kq = f & 3;
            int kg = k0 + kq * 4;
            {
                int m = m0 + mm, t = m >> 6, b = m & 63;
                const float* xp = &x[((size_t)b * T + t) * NI + kg];
                float4 v;
                if (kg + 3 < NI) v = *(const float4*)xp;
                else {
                    v.x = (kg + 0 < NI) ? xp[0] : 0.f;
                    v.y = (kg + 1 < NI) ? xp[1] : 0.f;
                    v.z = (kg + 2 < NI) ? xp[2] : 0.f;
                    v.w = (kg + 3 < NI) ? xp[3] : 0.f;
                }
                va[rep] = v;
            }
            {
                int n = n0 + mm;
                const float* wp = &w1[(size_t)n * NI + kg];
                float4 v;
                if (kg + 3 < NI) v = *(const float4*)wp;
                else {
                    v.x = (kg + 0 < NI) ? wp[0] : 0.f;
                    v.y = (kg + 1 < NI) ? wp[1] : 0.f;
                    v.z = (kg + 2 < NI) ? wp[2] : 0.f;
                    v.w = (kg + 3 < NI) ? wp[3] : 0.f;
                }
                vb[rep] = v;
            }
        }
    };
    auto sttile = [&]() {
#pragma unroll
        for (int rep = 0; rep < 2; rep++) {
            int f = tid + rep * 256;
            int mm = f >> 2, kq = f & 3;
            As[kq * 4 + 0][mm] = va[rep].x; As[kq * 4 + 1][mm] = va[rep].y;
            As[kq * 4 + 2][mm] = va[rep].z; As[kq * 4 + 3][mm] = va[rep].w;
            Bs[kq * 4 + 0][mm] = vb[rep].x; Bs[kq * 4 + 1][mm] = vb[rep].y;
            Bs[kq * 4 + 2][mm] = vb[rep].z; Bs[kq * 4 + 3][mm] = vb[rep].w;
        }
    };

    ldtile(0);
    for (int k0 = 0; k0 < NI; k0 += 16) {
        sttile();
        __syncthreads();
        if (k0 + 16 < NI) ldtile(k0 + 16);
#pragma unroll
        for (int k = 0; k < 16; k++) {
            float a[8], bb[8];
#pragma unroll
            for (int i = 0; i < 4; i++) {
                a[i]      = As[k][ty * 4 + i];
                a[4 + i]  = As[k][64 + ty * 4 + i];
                bb[i]     = Bs[k][tx * 4 + i];
                bb[4 + i] = Bs[k][64 + tx * 4 + i];
            }
#pragma unroll
            for (int i = 0; i < 8; i++)
#pragma unroll
                for (int j = 0; j < 8; j++) acc[i][j] += a[i] * bb[j];
        }
        __syncthreads();
    }
#pragma unroll
    for (int i = 0; i < 8; i++) {
        int m = m0 + ((i < 4) ? ty * 4 + i : 64 + ty * 4 + (i - 4));
#pragma unroll
        for (int j = 0; j < 8; j++) {
            int n = n0 + ((j < 4) ? tx * 4 + j : 64 + tx * 4 + (j - 4));
            g_XP[(size_t)m * NH + n] = acc[i][j];
        }
    }
}

// ---------------- forward: 128 threads/sample, float4 gather (unchanged) ----------------
__global__ __launch_bounds__(128) void k_forward(const float* __restrict__ wrec) {
    __shared__ int list[NH + 64];
    __shared__ unsigned zmask[16];
    int b = blockIdx.x;
    int q = threadIdx.x;
    int lane = q & 31, w = q >> 5;

    const float4* wrec4 = (const float4*)wrec;
    float4 hm = {0,0,0,0}, tr = {0,0,0,0}, zs = {0,0,0,0};
    int nact = 0;

    for (int t = 0; t < T; t++) {
        float4 xp = __ldg((const float4*)&g_XP[((size_t)t * B + b) * NH] + q);
        float4 acc = {0,0,0,0};
        if (nact > 0) {
            float4 v0[16], v1[16];
            auto ldwin = [&](int k, float4* v) {
#pragma unroll
                for (int u = 0; u < 16; u++) {
                    int ix = k * 16 + u;
                    float4 zz = {0.f, 0.f, 0.f, 0.f};
                    v[u] = (ix < nact) ? __ldg(&wrec4[(size_t)list[ix] * 128 + q]) : zz;
                }
            };
            auto sumwin = [&](const float4* v) {
#pragma unroll
                for (int u = 0; u < 16; u++) {
                    acc.x += v[u].x; acc.y += v[u].y; acc.z += v[u].z; acc.w += v[u].w;
                }
            };
            int npairs = (nact + 31) >> 5;
            ldwin(0, v0);
            for (int p = 0; p < npairs; p++) {
                ldwin(2 * p + 1, v1);
                sumwin(v0);
                ldwin(2 * p + 2, v0);
                sumwin(v1);
            }
        }
        float4 z, ht;
        hm.x = TAUc * hm.x * (1.f - zs.x) + xp.x + acc.x;
        hm.y = TAUc * hm.y * (1.f - zs.y) + xp.y + acc.y;
        hm.z = TAUc * hm.z * (1.f - zs.z) + xp.z + acc.z;
        hm.w = TAUc * hm.w * (1.f - zs.w) + xp.w + acc.w;
        z.x = (hm.x >= THRc) ? 1.f : 0.f;
        z.y = (hm.y >= THRc) ? 1.f : 0.f;
        z.z = (hm.z >= THRc) ? 1.f : 0.f;
        z.w = (hm.w >= THRc) ? 1.f : 0.f;
        ht.x = TAUc * fmaxf(0.f, 1.f - fabsf((hm.x - THRc) * (1.f / THRc)));
        ht.y = TAUc * fmaxf(0.f, 1.f - fabsf((hm.y - THRc) * (1.f / THRc)));
        ht.z = TAUc * fmaxf(0.f, 1.f - fabsf((hm.z - THRc) * (1.f / THRc)));
        ht.w = TAUc * fmaxf(0.f, 1.f - fabsf((hm.w - THRc) * (1.f / THRc)));
        tr.x = TAUc * tr.x + zs.x;
        tr.y = TAUc * tr.y + zs.y;
        tr.z = TAUc * tr.z + zs.z;
        tr.w = TAUc * tr.w + zs.w;
        size_t o4 = ((size_t)t * B + b) * 128 + q;
        ((float4*)g_Z)[o4] = z; ((float4*)g_HT)[o4] = ht; ((float4*)g_TREC)[o4] = tr;
        zs = z;

        unsigned nib = (z.x != 0.f ? 1u : 0u) | (z.y != 0.f ? 2u : 0u)
                     | (z.z != 0.f ? 4u : 0u) | (z.w != 0.f ? 8u : 0u);
        unsigned word = nib << ((lane & 7) * 4);
        word |= __shfl_xor_sync(0xffffffffu, word, 1);
        word |= __shfl_xor_sync(0xffffffffu, word, 2);
        word |= __shfl_xor_sync(0xffffffffu, word, 4);
        if ((lane & 7) == 0) zmask[w * 4 + (lane >> 3)] = word;
        __syncthreads();

        int tot = 0, pre = 0;
        int myc = q >> 3;
#pragma unroll
        for (int c = 0; c < 16; c++) {
            int pc = __popc(zmask[c]);
            if (c < myc) pre += pc;
            tot += pc;
        }
        pre += __popc(zmask[myc] & ((1u << ((q & 7) * 4)) - 1u));
        nact = tot;
        if (nib & 1u) list[pre++] = 4 * q + 0;
        if (nib & 2u) list[pre++] = 4 * q + 1;
        if (nib & 4u) list[pre++] = 4 * q + 2;
        if (nib & 8u) list[pre++] = 4 * q + 3;
        __syncthreads();
    }
}

// ---------------- S[m,o] = Z[m,:] . wout[o,:]  (200 blocks, 32 rows each) ----------------
__global__ __launch_bounds__(256) void k_s(const float* __restrict__ wout) {
    __shared__ float ws[NO * NH];
    int m0 = blockIdx.x * 32;
    int tid = threadIdx.x, w = tid >> 5, lane = tid & 31;
    for (int i = tid; i < NO * NH; i += 256) ws[i] = wout[i];
    __syncthreads();
#pragma unroll 1
    for (int r = 0; r < 4; r++) {
        int m = m0 + w * 4 + r;
        float zv[16];
#pragma unroll
        for (int c = 0; c < 16; c++) zv[c] = g_Z[(size_t)m * NH + c * 32 + lane];
#pragma unroll 1
        for (int o = 0; o < NO; o++) {
            float s = 0.f;
#pragma unroll
            for (int c = 0; c < 16; c++) s += zv[c] * ws[o * NH + c * 32 + lane];
#pragma unroll
            for (int off = 16; off; off >>= 1) s += __shfl_xor_sync(0xffffffffu, s, off);
            if (lane == 0) g_S[(size_t)m * NO + o] = s;
        }
    }
}

// ---------------- output LIF scan + reverse kappa filter ----------------
__global__ void k_scan(const float* __restrict__ label, float* __restrict__ out) {
    int n = blockIdx.x * 256 + threadIdx.x;
    if (n >= B * NO) return;
    int b = n / NO, o = n - b * NO;
    float om = 0.f, os = 0.f;
    for (int t = 0; t < T; t += 4) {
        float sv[4], lv[4];
#pragma unroll
        for (int u = 0; u < 4; u++) {
            sv[u] = g_S[((size_t)(t + u) * B + b) * NO + o];
            lv[u] = label[((size_t)b * T + t + u) * NO + o];
        }
#pragma unroll
        for (int u = 0; u < 4; u++) {
            om = TAUc * om * (1.f - os) + sv[u];
            os = (om >= THRc) ? 1.f : 0.f;
            out[((size_t)b * T + t + u) * NO + o] = os;
            g_EF[((size_t)(t + u) * B + b) * NO + o] = os - lv[u];
        }
    }
    float ef = 0.f;
    for (int t = T - 4; t >= 0; t -= 4) {
        float ev[4];
#pragma unroll
        for (int u = 0; u < 4; u++) ev[u] = g_EF[((size_t)(t + u) * B + b) * NO + o];
#pragma unroll
        for (int u = 3; u >= 0; u--) {
            ef = ev[u] + KAPc * ef;
            g_EF[((size_t)(t + u) * B + b) * NO + o] = ef;
        }
    }
}

// ---------------- A[m,r] = (EF[m,:] . wout[:,r]) * HT[m,r] ----------------
__global__ void k_A(const float* __restrict__ wout) {
    int gid = blockIdx.x * 256 + threadIdx.x;
    if (gid >= T * B * NH) return;
    int m = gid >> 9;
    int r = gid & (NH - 1);
    const float* ef = g_EF + (size_t)m * NO;
    float L = 0.f;
#pragma unroll
    for (int o = 0; o < NO; o++) L += ef[o] * wout[o * NH + r];
    g_A[gid] = L * g_HT[gid];
}

// ---------------- gemm bodies (device) ----------------
__device__ __forceinline__ void gemm128_body(
    const float* __restrict__ A, int sA,
    const float* __restrict__ Bm, int sB,
    float* __restrict__ C, int N,
    int m0, int n0, int kts, int kte,
    float* __restrict__ As, float* __restrict__ Bs)   // [16*128] each
{
    int tid = threadIdx.x, tx = tid & 15, ty = tid >> 4;
    float acc[8][8] = {};
    float4 va[2], vb[2];

    auto ldtile = [&](int kt) {
        int k0 = kt * 16;
#pragma unroll
        for (int rep = 0; rep < 2; rep++) {
            int f = tid + rep * 256;
            int kk = f >> 5, c4 = (f & 31) * 4;
            va[rep] = *(const float4*)&A[(size_t)(k0 + kk) * sA + m0 + c4];
            int n = n0 + c4;
            const float* bp = &Bm[(size_t)(k0 + kk) * sB + n];
            float4 bv;
            if (n + 3 < N) bv = *(const float4*)bp;
            else {
                bv.x = (n + 0 < N) ? bp[0] : 0.f;
                bv.y = (n + 1 < N) ? bp[1] : 0.f;
                bv.z = (n + 2 < N) ? bp[2] : 0.f;
                bv.w = (n + 3 < N) ? bp[3] : 0.f;
            }
            vb[rep] = bv;
        }
    };
    auto sttile = [&]() {
#pragma unroll
        for (int rep = 0; rep < 2; rep++) {
            int f = tid + rep * 256;
            int kk = f >> 5, c4 = (f & 31) * 4;
            *(float4*)&As[kk * 128 + c4] = va[rep];
            *(float4*)&Bs[kk * 128 + c4] = vb[rep];
        }
    };

    ldtile(kts);
    for (int kt = kts; kt < kte; kt++) {
        sttile();
        __syncthreads();
        if (kt + 1 < kte) ldtile(kt + 1);
#pragma unroll
        for (int k = 0; k < 16; k++) {
            float a[8], bb[8];
            *(float4*)&a[0]  = *(float4*)&As[k * 128 + ty * 4];
            *(float4*)&a[4]  = *(float4*)&As[k * 128 + 64 + ty * 4];
            *(float4*)&bb[0] = *(float4*)&Bs[k * 128 + tx * 4];
            *(float4*)&bb[4] = *(float4*)&Bs[k * 128 + 64 + tx * 4];
#pragma unroll
            for (int i = 0; i < 8; i++)
#pragma unroll
                for (int j = 0; j < 8; j++) acc[i][j] += a[i] * bb[j];
        }
        __syncthreads();
    }
#pragma unroll
    for (int i = 0; i < 8; i++) {
        int m = m0 + ((i < 4) ? ty * 4 + i : 64 + ty * 4 + (i - 4));
#pragma unroll
        for (int j = 0; j < 8; j++) {
            int n = n0 + ((j < 4) ? tx * 4 + j : 64 + tx * 4 + (j - 4));
            if (n < N) C[(size_t)m * N + n] = acc[i][j];
        }
    }
}

__device__ __forceinline__ void gemm64_body(
    const float* __restrict__ A, int sA,
    const float* __restrict__ Bm, int sB,
    float* __restrict__ C, int M, int N,
    int m0, int n0, int k0s, int k0e,
    float* __restrict__ As, float* __restrict__ Bs)   // [16*64] each
{
    int tid = threadIdx.x, tx = tid & 15, ty = tid >> 4;
    float acc[4][4] = {};
    for (int k0 = k0s; k0 < k0e; k0 += 16) {
#pragma unroll
        for (int rep = 0; rep < 4; rep++) {
            int e = tid + rep * 256;
            int mm = e & 63, kk = e >> 6;
            int mg = m0 + mm;
            As[kk * 64 + mm] = (mg < M) ? A[(size_t)(k0 + kk) * sA + mg] : 0.f;
            int ng = n0 + mm;
            Bs[kk * 64 + mm] = (ng < N) ? Bm[(size_t)(k0 + kk) * sB + ng] : 0.f;
        }
        __syncthreads();
#pragma unroll
        for (int k = 0; k < 16; k++) {
            float a[4], bb[4];
#pragma unroll
            for (int i = 0; i < 4; i++) a[i]  = As[k * 64 + ty * 4 + i];
#pragma unroll
            for (int j = 0; j < 4; j++) bb[j] = Bs[k * 64 + tx * 4 + j];
#pragma unroll
            for (int i = 0; i < 4; i++)
#pragma unroll
                for (int j = 0; j < 4; j++) acc[i][j] += a[i] * bb[j];
        }
        __syncthreads();
    }
#pragma unroll
    for (int i = 0; i < 4; i++) {
        int m = m0 + ty * 4 + i;
        if (m < M) {
#pragma unroll
            for (int j = 0; j < 4; j++) {
                int n = n0 + tx * 4 + j;
                if (n < N) C[(size_t)m * N + n] = acc[i][j];
            }
        }
    }
}

// ---------------- fused gradients: gf(168) + gr(128) + go(64) = 360 blocks ----------------
// gf: splitK 7 (ktile splits 57..58), gr: splitK 8 (50 ktiles) -> 296 heavy blocks = 2/SM.
__global__ __launch_bounds__(256, 2) void k_grads() {
    __shared__ float As[16 * 128];
    __shared__ float Bs[16 * 128];
    int bid = blockIdx.x;
    if (bid < 168) {
        // gf partial: A^T(g_A) @ g_TIN -> [512 x 700]
        int z = bid / 24, rem = bid - z * 24;
        int n0 = (rem % 6) * 128, m0 = (rem / 6) * 128;
        const int kst[8] = {0, 57, 114, 171, 228, 285, 342, 400};
        gemm128_body(g_A, NH, g_TIN, NI,
                     g_gp + GFP_OFF + (size_t)z * GF_MN, NI,
                     m0, n0, kst[z], kst[z + 1], As, Bs);
    } else if (bid < 296) {
        // gr partial: A^T(g_A) @ g_TREC -> [512 x 512]
        int i = bid - 168;
        int z = i / 16, rem = i - z * 16;
        int n0 = (rem % 4) * 128, m0 = (rem / 4) * 128;
        gemm128_body(g_A, NH, g_TREC, NH,
                     g_gp + GRP_OFF + (size_t)z * GR_MN, NH,
                     m0, n0, z * 50, z * 50 + 50, As, Bs);
    } else {
        // go partial: EF^T @ Z -> [20 x 512]
        int i = bid - 296;
        int z = i / 8, nx = i - z * 8;
        gemm64_body(g_EF, NO, g_Z, NH,
                    g_gp + GOP_OFF + (size_t)z * GO_MN, NO, NH,
                    0, nx * 64, z * 800, z * 800 + 800, As, Bs);
    }
}

// ---------------- fused reduce over all three gradient outputs ----------------
__global__ void k_redAll(float* __restrict__ gf, float* __restrict__ gr,
                         float* __restrict__ go) {
    int i = blockIdx.x * 256 + threadIdx.x;
    if (i < GF_MN) {
        float s = 0.f;
#pragma unroll
        for (int z = 0; z < 7; z++) s += g_gp[GFP_OFF + (size_t)z * GF_MN + i];
        gf[i] = LRc * s;
    } else if (i < GF_MN + GR_MN) {
        int j = i - GF_MN;
        float s = 0.f;
#pragma unroll
        for (int z = 0; z < 8; z++) s += g_gp[GRP_OFF + (size_t)z * GR_MN + j];
        gr[j] = LRc * s;
    } else if (i < GF_MN + GR_MN + GO_MN) {
        int j = i - GF_MN - GR_MN;
        float s = 0.f;
#pragma unroll
        for (int z = 0; z < 8; z++) s += g_gp[GOP_OFF + (size_t)z * GO_MN + j];
        go[j] = LRc * s;
    }
}

// ---------------- launch ----------------
extern "C" void kernel_launch(void* const* d_in, const int* in_sizes, int n_in,
                              void* d_out, int out_size) {
    const float* x     = (const float*)d_in[0];
    const float* label = (const float*)d_in[1];
    const float* w1    = (const float*)d_in[3];
    const float* wrec  = (const float*)d_in[4];
    const float* wout  = (const float*)d_in[5];
    float* out = (float*)d_out;
    float* gf = out + B * T * NO;          // [NH, NI]
    float* gr = gf + NH * NI;              // [NH, NH]
    float* go = gr + NH * NH;              // [NO, NH]

    k_head<<<375, 256>>>(x, w1);           // gemmX (fp32, precision-critical) || tin
    k_forward<<<B, 128>>>(wrec);
    k_s<<<200, 256>>>(wout);
    k_scan<<<5, 256>>>(label, out);
    k_A<<<(T * B * NH + 255) / 256, 256>>>(wout);
    k_grads<<<360, 256>>>();               // gf || gr || go, 296 heavy blocks = 2/SM
    k_redAll<<<(GF_MN + GR_MN + GO_MN + 255) / 256, 256>>>(gf, gr, go);
}

// round 13
// speedup vs baseline: 2.2455x; 1.1516x over previous
#include <cuda_runtime.h>

#define B   64
#define T   100
#define NI  700
#define NH  512
#define NO  20
#define TAUc 0.6f
#define KAPc 0.6f
#define THRc 0.6f
#define LRc  0.05f

// ---------------- persistent device scratch ----------------
__device__ float g_XP  [T*B*NH];   // x @ W1^T, rows m = t*B+b
__device__ float g_TIN [T*B*NI];
__device__ float g_TREC[T*B*NH];
__device__ float g_HT  [T*B*NH];
__device__ float g_Z   [T*B*NH];
__device__ float g_EF  [T*B*NO];
__device__ float g_A   [T*B*NH];
__device__ unsigned g_ready[64];   // per-m-tile XP readiness (4 n-tiles each)

// gradient split-K partials: gf 7 parts, gr 8 parts, go 8 parts
#define GF_MN (NH*NI)
#define GR_MN (NH*NH)
#define GO_MN (NO*NH)
#define GFP_OFF 0
#define GRP_OFF (7*GF_MN)
#define GOP_OFF (GRP_OFF + 8*GR_MN)
__device__ float g_gp[GOP_OFF + 8*GO_MN];

// k_main dynamic smem: forward path needs the max
// ws[NO*NH] + zsh[NH] + errh[T*NO] + list[NH+64] + zmask[16] = 13344 words
#define MAIN_SMEM (13344 * 4)

// ============================================================================
// k_main: gemmX blocks [0,200) | forward blocks [200,264) | tin blocks [264,439)
// ============================================================================
__global__ __launch_bounds__(256, 2) void k_main(const float* __restrict__ x,
                                                 const float* __restrict__ w1,
                                                 const float* __restrict__ wrec,
                                                 const float* __restrict__ wout,
                                                 const float* __restrict__ label,
                                                 float* __restrict__ out) {
    extern __shared__ char smraw[];
    int bid = blockIdx.x;
    int tid = threadIdx.x;

    if (bid < 200) {
        // ---------------- gemmX: Xproj = X @ W1^T (fp32, PRECISION-CRITICAL) ----------------
        float (*As)[129] = (float(*)[129])smraw;
        float (*Bs)[129] = (float(*)[129])(smraw + 16 * 129 * 4);
        int m0 = (bid >> 2) * 128, n0 = (bid & 3) * 128;
        int tx = tid & 15, ty = tid >> 4;
        float acc[8][8] = {};
        float4 va[2], vb[2];

        auto ldtile = [&](int k0) {
#pragma unroll
            for (int rep = 0; rep < 2; rep++) {
                int f = tid + rep * 256;
                int mm = f >> 2, kq = f & 3;
                int kg = k0 + kq * 4;
                {
                    int m = m0 + mm, t = m >> 6, b = m & 63;
                    const float* xp = &x[((size_t)b * T + t) * NI + kg];
                    float4 v;
                    if (kg + 3 < NI) v = *(const float4*)xp;
                    else {
                        v.x = (kg + 0 < NI) ? xp[0] : 0.f;
                        v.y = (kg + 1 < NI) ? xp[1] : 0.f;
                        v.z = (kg + 2 < NI) ? xp[2] : 0.f;
                        v.w = (kg + 3 < NI) ? xp[3] : 0.f;
                    }
                    va[rep] = v;
                }
                {
                    int n = n0 + mm;
                    const float* wp = &w1[(size_t)n * NI + kg];
                    float4 v;
                    if (kg + 3 < NI) v = *(const float4*)wp;
                    else {
                        v.x = (kg + 0 < NI) ? wp[0] : 0.f;
                        v.y = (kg + 1 < NI) ? wp[1] : 0.f;
                        v.z = (kg + 2 < NI) ? wp[2] : 0.f;
                        v.w = (kg + 3 < NI) ? wp[3] : 0.f;
                    }
                    vb[rep] = v;
                }
            }
        };
        auto sttile = [&]() {
#pragma unroll
            for (int rep = 0; rep < 2; rep++) {
                int f = tid + rep * 256;
                int mm = f >> 2, kq = f & 3;
                As[kq * 4 + 0][mm] = va[rep].x; As[kq * 4 + 1][mm] = va[rep].y;
                As[kq * 4 + 2][mm] = va[rep].z; As[kq * 4 + 3][mm] = va[rep].w;
                Bs[kq * 4 + 0][mm] = vb[rep].x; Bs[kq * 4 + 1][mm] = vb[rep].y;
                Bs[kq * 4 + 2][mm] = vb[rep].z; Bs[kq * 4 + 3][mm] = vb[rep].w;
            }
        };

        ldtile(0);
        for (int k0 = 0; k0 < NI; k0 += 16) {
            sttile();
            __syncthreads();
            if (k0 + 16 < NI) ldtile(k0 + 16);
#pragma unroll
            for (int k = 0; k < 16; k++) {
                float a[8], bb[8];
#pragma unroll
                for (int i = 0; i < 4; i++) {
                    a[i]      = As[k][ty * 4 + i];
                    a[4 + i]  = As[k][64 + ty * 4 + i];
                    bb[i]     = Bs[k][tx * 4 + i];
                    bb[4 + i] = Bs[k][64 + tx * 4 + i];
                }
#pragma unroll
                for (int i = 0; i < 8; i++)
#pragma unroll
                    for (int j = 0; j < 8; j++) acc[i][j] += a[i] * bb[j];
            }
            __syncthreads();
        }
#pragma unroll
        for (int i = 0; i < 8; i++) {
            int m = m0 + ((i < 4) ? ty * 4 + i : 64 + ty * 4 + (i - 4));
#pragma unroll
            for (int j = 0; j < 8; j++) {
                int n = n0 + ((j < 4) ? tx * 4 + j : 64 + tx * 4 + (j - 4));
                g_XP[(size_t)m * NH + n] = acc[i][j];
            }
        }
        __threadfence();               // device-visible before ready signal
        __syncthreads();
        if (tid == 0) atomicAdd(&g_ready[bid >> 2], 1u);
        return;
    }

    if (bid >= 264) {
        // ---------------- tin scan ----------------
        int n = (bid - 264) * 256 + tid;
        if (n < B * NI) {
            int b = n / NI, i = n - b * NI;
            float tv = 0.f;
            for (int t = 0; t < T; t++) {
                tv = TAUc * tv + x[(b * T + t) * NI + i];
                g_TIN[((size_t)t * B + b) * NI + i] = tv;
            }
        }
        return;
    }

    // ---------------- forward (+ fused output LIF + reverse filter) ----------------
    float* ws   = (float*)smraw;            // NO*NH
    float* zsh  = ws + NO * NH;             // NH
    float* errh = zsh + NH;                 // T*NO
    int*   list = (int*)(errh + T * NO);    // NH+64
    unsigned* zmask = (unsigned*)(list + NH + 64);   // 16

    int b = bid - 200;
    int q = tid;                    // neuron threads use q<128
    int lane = tid & 31, w = tid >> 5;
    bool is_n = (tid < 128);
    int ow = w - 4;                 // output warps 4..7

    for (int i = tid; i < NO * NH; i += 256) ws[i] = wout[i];
    for (int i = tid; i < NH; i += 256) zsh[i] = 0.f;
    __syncthreads();

    const float4* wrec4 = (const float4*)wrec;
    float4 hm = {0,0,0,0}, tr = {0,0,0,0}, zs = {0,0,0,0};
    float om[5] = {}, os[5] = {};
    int nact = 0, pdone = -1;

    auto do_out = [&](int tp) {
#pragma unroll
        for (int qq = 0; qq < 5; qq++) {
            int o = ow * 5 + qq;
            float s = 0.f;
#pragma unroll
            for (int c = 0; c < 16; c++)
                s += zsh[c * 32 + lane] * ws[o * NH + c * 32 + lane];
#pragma unroll
            for (int off = 16; off; off >>= 1) s += __shfl_xor_sync(0xffffffffu, s, off);
            om[qq] = TAUc * om[qq] * (1.f - os[qq]) + s;
            os[qq] = (om[qq] >= THRc) ? 1.f : 0.f;
            if (lane == 0) {
                out[((size_t)b * T + tp) * NO + o] = os[qq];
                errh[tp * NO + o] = os[qq] - label[((size_t)b * T + tp) * NO + o];
            }
        }
    };

    for (int t = 0; t < T; t++) {
        float4 z = {0,0,0,0};
        unsigned nib = 0;
        if (is_n) {
            int p = t >> 1;
            if (p > pdone) {
                while (((volatile unsigned*)g_ready)[p] < 4u) {}
                pdone = p;
            }
            float4 xp;
            {
                const float4* xp4 = (const float4*)&g_XP[((size_t)t * B + b) * NH] + q;
                xp.x = __ldcg(&xp4->x); xp.y = __ldcg(&xp4->y);
                xp.z = __ldcg(&xp4->z); xp.w = __ldcg(&xp4->w);
            }
            float4 acc = {0,0,0,0};
            for (int i = 0; i < nact; i += 16) {
                float4 v[16];
#pragma unroll
                for (int u = 0; u < 16; u++) {
                    int ix = i + u;
                    float4 zz = {0.f, 0.f, 0.f, 0.f};
                    v[u] = (ix < nact) ? __ldg(&wrec4[(size_t)list[ix] * 128 + q]) : zz;
                }
#pragma unroll
                for (int u = 0; u < 16; u++) {
                    acc.x += v[u].x; acc.y += v[u].y; acc.z += v[u].z; acc.w += v[u].w;
                }
            }
            float4 ht;
            hm.x = TAUc * hm.x * (1.f - zs.x) + xp.x + acc.x;
            hm.y = TAUc * hm.y * (1.f - zs.y) + xp.y + acc.y;
            hm.z = TAUc * hm.z * (1.f - zs.z) + xp.z + acc.z;
            hm.w = TAUc * hm.w * (1.f - zs.w) + xp.w + acc.w;
            z.x = (hm.x >= THRc) ? 1.f : 0.f;
            z.y = (hm.y >= THRc) ? 1.f : 0.f;
            z.z = (hm.z >= THRc) ? 1.f : 0.f;
            z.w = (hm.w >= THRc) ? 1.f : 0.f;
            ht.x = TAUc * fmaxf(0.f, 1.f - fabsf((hm.x - THRc) * (1.f / THRc)));
            ht.y = TAUc * fmaxf(0.f, 1.f - fabsf((hm.y - THRc) * (1.f / THRc)));
            ht.z = TAUc * fmaxf(0.f, 1.f - fabsf((hm.z - THRc) * (1.f / THRc)));
            ht.w = TAUc * fmaxf(0.f, 1.f - fabsf((hm.w - THRc) * (1.f / THRc)));
            tr.x = TAUc * tr.x + zs.x;
            tr.y = TAUc * tr.y + zs.y;
            tr.z = TAUc * tr.z + zs.z;
            tr.w = TAUc * tr.w + zs.w;
            size_t o4 = ((size_t)t * B + b) * 128 + q;
            ((float4*)g_Z)[o4] = z; ((float4*)g_HT)[o4] = ht; ((float4*)g_TREC)[o4] = tr;
            zs = z;

            nib = (z.x != 0.f ? 1u : 0u) | (z.y != 0.f ? 2u : 0u)
                | (z.z != 0.f ? 4u : 0u) | (z.w != 0.f ? 8u : 0u);
            unsigned word = nib << ((lane & 7) * 4);
            word |= __shfl_xor_sync(0xffffffffu, word, 1);
            word |= __shfl_xor_sync(0xffffffffu, word, 2);
            word |= __shfl_xor_sync(0xffffffffu, word, 4);
            if ((lane & 7) == 0) zmask[w * 4 + (lane >> 3)] = word;
        } else if (w >= 4 && t > 0) {
            do_out(t - 1);          // reads zsh = z_{t-1}
        }
        __syncthreads();            // zsh consumers + gather done; zmask ready

        if (is_n) {
            *(float4*)&zsh[4 * q] = z;
            int tot = 0, pre = 0;
            int myc = q >> 3;
#pragma unroll
            for (int c = 0; c < 16; c++) {
                int pc = __popc(zmask[c]);
                if (c < myc) pre += pc;
                tot += pc;
            }
            pre += __popc(zmask[myc] & ((1u << ((q & 7) * 4)) - 1u));
            nact = tot;
            if (nib & 1u) list[pre++] = 4 * q + 0;
            if (nib & 2u) list[pre++] = 4 * q + 1;
            if (nib & 4u) list[pre++] = 4 * q + 2;
            if (nib & 8u) list[pre++] = 4 * q + 3;
        }
        __syncthreads();            // zsh/list ready for next step
    }
    if (!is_n && w >= 4) do_out(T - 1);
    __syncthreads();

    // fused reverse kappa filter
    if (tid < NO) {
        float ef = 0.f;
        for (int t = T - 1; t >= 0; t--) {
            ef = errh[t * NO + tid] + KAPc * ef;
            g_EF[((size_t)t * B + b) * NO + tid] = ef;
        }
    }
}

// ---------------- A[m,r] = (EF[m,:] . wout[:,r]) * HT[m,r] ----------------
__global__ void k_A(const float* __restrict__ wout) {
    int gid = blockIdx.x * 256 + threadIdx.x;
    if (gid >= T * B * NH) return;
    int m = gid >> 9;
    int r = gid & (NH - 1);
    const float* ef = g_EF + (size_t)m * NO;
    float L = 0.f;
#pragma unroll
    for (int o = 0; o < NO; o++) L += ef[o] * wout[o * NH + r];
    g_A[gid] = L * g_HT[gid];
}

// ---------------- gemm bodies (device) ----------------
__device__ __forceinline__ void gemm128_body(
    const float* __restrict__ A, int sA,
    const float* __restrict__ Bm, int sB,
    float* __restrict__ C, int N,
    int m0, int n0, int kts, int kte,
    float* __restrict__ As, float* __restrict__ Bs)
{
    int tid = threadIdx.x, tx = tid & 15, ty = tid >> 4;
    float acc[8][8] = {};
    float4 va[2], vb[2];

    auto ldtile = [&](int kt) {
        int k0 = kt * 16;
#pragma unroll
        for (int rep = 0; rep < 2; rep++) {
            int f = tid + rep * 256;
            int kk = f >> 5, c4 = (f & 31) * 4;
            va[rep] = *(const float4*)&A[(size_t)(k0 + kk) * sA + m0 + c4];
            int n = n0 + c4;
            const float* bp = &Bm[(size_t)(k0 + kk) * sB + n];
            float4 bv;
            if (n + 3 < N) bv = *(const float4*)bp;
            else {
                bv.x = (n + 0 < N) ? bp[0] : 0.f;
                bv.y = (n + 1 < N) ? bp[1] : 0.f;
                bv.z = (n + 2 < N) ? bp[2] : 0.f;
                bv.w = (n + 3 < N) ? bp[3] : 0.f;
            }
            vb[rep] = bv;
        }
    };
    auto sttile = [&]() {
#pragma unroll
        for (int rep = 0; rep < 2; rep++) {
            int f = tid + rep * 256;
            int kk = f >> 5, c4 = (f & 31) * 4;
            *(float4*)&As[kk * 128 + c4] = va[rep];
            *(float4*)&Bs[kk * 128 + c4] = vb[rep];
        }
    };

    ldtile(kts);
    for (int kt = kts; kt < kte; kt++) {
        sttile();
        __syncthreads();
        if (kt + 1 < kte) ldtile(kt + 1);
#pragma unroll
        for (int k = 0; k < 16; k++) {
            float a[8], bb[8];
            *(float4*)&a[0]  = *(float4*)&As[k * 128 + ty * 4];
            *(float4*)&a[4]  = *(float4*)&As[k * 128 + 64 + ty * 4];
            *(float4*)&bb[0] = *(float4*)&Bs[k * 128 + tx * 4];
            *(float4*)&bb[4] = *(float4*)&Bs[k * 128 + 64 + tx * 4];
#pragma unroll
            for (int i = 0; i < 8; i++)
#pragma unroll
                for (int j = 0; j < 8; j++) acc[i][j] += a[i] * bb[j];
        }
        __syncthreads();
    }
#pragma unroll
    for (int i = 0; i < 8; i++) {
        int m = m0 + ((i < 4) ? ty * 4 + i : 64 + ty * 4 + (i - 4));
#pragma unroll
        for (int j = 0; j < 8; j++) {
            int n = n0 + ((j < 4) ? tx * 4 + j : 64 + tx * 4 + (j - 4));
            if (n < N) C[(size_t)m * N + n] = acc[i][j];
        }
    }
}

__device__ __forceinline__ void gemm64_body(
    const float* __restrict__ A, int sA,
    const float* __restrict__ Bm, int sB,
    float* __restrict__ C, int M, int N,
    int m0, int n0, int k0s, int k0e,
    float* __restrict__ As, float* __restrict__ Bs)
{
    int tid = threadIdx.x, tx = tid & 15, ty = tid >> 4;
    float acc[4][4] = {};
    for (int k0 = k0s; k0 < k0e; k0 += 16) {
#pragma unroll
        for (int rep = 0; rep < 4; rep++) {
            int e = tid + rep * 256;
            int mm = e & 63, kk = e >> 6;
            int mg = m0 + mm;
            As[kk * 64 + mm] = (mg < M) ? A[(size_t)(k0 + kk) * sA + mg] : 0.f;
            int ng = n0 + mm;
            Bs[kk * 64 + mm] = (ng < N) ? Bm[(size_t)(k0 + kk) * sB + ng] : 0.f;
        }
        __syncthreads();
#pragma unroll
        for (int k = 0; k < 16; k++) {
            float a[4], bb[4];
#pragma unroll
            for (int i = 0; i < 4; i++) a[i]  = As[k * 64 + ty * 4 + i];
#pragma unroll
            for (int j = 0; j < 4; j++) bb[j] = Bs[k * 64 + tx * 4 + j];
#pragma unroll
            for (int i = 0; i < 4; i++)
#pragma unroll
                for (int j = 0; j < 4; j++) acc[i][j] += a[i] * bb[j];
        }
        __syncthreads();
    }
#pragma unroll
    for (int i = 0; i < 4; i++) {
        int m = m0 + ty * 4 + i;
        if (m < M) {
#pragma unroll
            for (int j = 0; j < 4; j++) {
                int n = n0 + tx * 4 + j;
                if (n < N) C[(size_t)m * N + n] = acc[i][j];
            }
        }
    }
}

// ---------------- fused gradients: gf(168) + gr(128) + go(64) = 360 blocks ----------------
__global__ __launch_bounds__(256, 2) void k_grads() {
    __shared__ float As[16 * 128];
    __shared__ float Bs[16 * 128];
    int bid = blockIdx.x;
    if (bid < 168) {
        int z = bid / 24, rem = bid - z * 24;
        int n0 = (rem % 6) * 128, m0 = (rem / 6) * 128;
        const int kst[8] = {0, 57, 114, 171, 228, 285, 342, 400};
        gemm128_body(g_A, NH, g_TIN, NI,
                     g_gp + GFP_OFF + (size_t)z * GF_MN, NI,
                     m0, n0, kst[z], kst[z + 1], As, Bs);
    } else if (bid < 296) {
        int i = bid - 168;
        int z = i / 16, rem = i - z * 16;
        int n0 = (rem % 4) * 128, m0 = (rem / 4) * 128;
        gemm128_body(g_A, NH, g_TREC, NH,
                     g_gp + GRP_OFF + (size_t)z * GR_MN, NH,
                     m0, n0, z * 50, z * 50 + 50, As, Bs);
    } else {
        int i = bid - 296;
        int z = i / 8, nx = i - z * 8;
        gemm64_body(g_EF, NO, g_Z, NH,
                    g_gp + GOP_OFF + (size_t)z * GO_MN, NO, NH,
                    0, nx * 64, z * 800, z * 800 + 800, As, Bs);
    }
}

// ---------------- fused reduce over all three gradient outputs ----------------
__global__ void k_redAll(float* __restrict__ gf, float* __restrict__ gr,
                         float* __restrict__ go) {
    int i = blockIdx.x * 256 + threadIdx.x;
    if (i < GF_MN) {
        float s = 0.f;
#pragma unroll
        for (int z = 0; z < 7; z++) s += g_gp[GFP_OFF + (size_t)z * GF_MN + i];
        gf[i] = LRc * s;
    } else if (i < GF_MN + GR_MN) {
        int j = i - GF_MN;
        float s = 0.f;
#pragma unroll
        for (int z = 0; z < 8; z++) s += g_gp[GRP_OFF + (size_t)z * GR_MN + j];
        gr[j] = LRc * s;
    } else if (i < GF_MN + GR_MN + GO_MN) {
        int j = i - GF_MN - GR_MN;
        float s = 0.f;
#pragma unroll
        for (int z = 0; z < 8; z++) s += g_gp[GOP_OFF + (size_t)z * GO_MN + j];
        go[j] = LRc * s;
    }
}

// ---------------- launch ----------------
extern "C" void kernel_launch(void* const* d_in, const int* in_sizes, int n_in,
                              void* d_out, int out_size) {
    const float* x     = (const float*)d_in[0];
    const float* label = (const float*)d_in[1];
    const float* w1    = (const float*)d_in[3];
    const float* wrec  = (const float*)d_in[4];
    const float* wout  = (const float*)d_in[5];
    float* out = (float*)d_out;
    float* gf = out + B * T * NO;          // [NH, NI]
    float* gr = gf + NH * NI;              // [NH, NH]
    float* go = gr + NH * NH;              // [NO, NH]

    cudaFuncSetAttribute(k_main, cudaFuncAttributeMaxDynamicSharedMemorySize, MAIN_SMEM);

    void* pR;
    cudaGetSymbolAddress(&pR, g_ready);
    cudaMemsetAsync(pR, 0, 64 * sizeof(unsigned));

    k_main<<<439, 256, MAIN_SMEM>>>(x, w1, wrec, wout, label, out);
    k_A<<<(T * B * NH + 255) / 256, 256>>>(wout);
    k_grads<<<360, 256>>>();
    k_redAll<<<(GF_MN + GR_MN + GO_MN + 255) / 256, 256>>>(gf, gr, go);
}

// round 14
// speedup vs baseline: 2.2796x; 1.0152x over previous
#include <cuda_runtime.h>

#define B   64
#define T   100
#define NI  700
#define NH  512
#define NO  20
#define TAUc 0.6f
#define KAPc 0.6f
#define THRc 0.6f
#define LRc  0.05f

// ---------------- persistent device scratch ----------------
__device__ float g_XP  [T*B*NH];   // x @ W1^T, rows m = t*B+b
__device__ float g_TIN [T*B*NI];
__device__ float g_TREC[T*B*NH];
__device__ float g_HT  [T*B*NH];
__device__ float g_Z   [T*B*NH];
__device__ float g_EF  [T*B*NO];
__device__ float g_A   [T*B*NH];
__device__ unsigned g_ready[64];   // per-m-tile XP readiness

// gradient split-K partials: gf 7 parts, gr 8 parts, go 8 parts
#define GF_MN (NH*NI)
#define GR_MN (NH*NH)
#define GO_MN (NO*NH)
#define GFP_OFF 0
#define GRP_OFF (7*GF_MN)
#define GOP_OFF (GRP_OFF + 8*GR_MN)
__device__ float g_gp[GOP_OFF + 8*GO_MN];

// k_main dynamic smem: forward path needs the max
#define MAIN_SMEM (13344 * 4)

// ============================================================================
// k_main block map:
//   [0,64)    forward (one sample each)          — scheduled FIRST
//   [64,128)  gemmX small tiles: m-tiles 0..7 as 64-row tiles (8 blocks per m-tile)
//   [128,296) gemmX 128-row tiles: m-tiles 8..49 (4 blocks per m-tile)
//   [296,471) tin scan
// Wave 1 = blocks 0..295 = 296 = exactly 2 per SM.
// ============================================================================
__global__ __launch_bounds__(256, 2) void k_main(const float* __restrict__ x,
                                                 const float* __restrict__ w1,
                                                 const float* __restrict__ wrec,
                                                 const float* __restrict__ wout,
                                                 const float* __restrict__ label,
                                                 float* __restrict__ out) {
    extern __shared__ char smraw[];
    int bid = blockIdx.x;
    int tid = threadIdx.x;

    if (bid >= 64 && bid < 128) {
        // ---------------- gemmX SMALL tile: 64 x 128, m-tiles 0..7 ----------------
        // Same per-element ascending-k FFMA chain as the 128-row tile -> bitwise identical.
        float (*As)[64]  = (float(*)[64])smraw;
        float (*Bs)[128] = (float(*)[128])(smraw + 16 * 64 * 4);
        int i = bid - 64;
        int p = i >> 3;                      // m-tile 0..7
        int sub = (i >> 2) & 1;              // top/bottom 64 rows
        int m0 = p * 128 + sub * 64;
        int n0 = (i & 3) * 128;
        int tx = tid & 15, ty = tid >> 4;
        float acc[4][8] = {};

        for (int k0 = 0; k0 < NI; k0 += 16) {
            // stage A: 64 rows x 16 k  (thread: mm = tid&63, kq = tid>>6)
            {
                int mm = tid & 63, kq = tid >> 6;
                int kg = k0 + kq * 4;
                int m = m0 + mm, t = m >> 6, b = m & 63;
                const float* xp = &x[((size_t)b * T + t) * NI + kg];
                float4 v;
                if (kg + 3 < NI) v = *(const float4*)xp;
                else {
                    v.x = (kg + 0 < NI) ? xp[0] : 0.f;
                    v.y = (kg + 1 < NI) ? xp[1] : 0.f;
                    v.z = (kg + 2 < NI) ? xp[2] : 0.f;
                    v.w = (kg + 3 < NI) ? xp[3] : 0.f;
                }
                As[kq * 4 + 0][mm] = v.x; As[kq * 4 + 1][mm] = v.y;
                As[kq * 4 + 2][mm] = v.z; As[kq * 4 + 3][mm] = v.w;
            }
            // stage B: 128 cols x 16 k (thread: nn = tid&127, kq = tid>>7; 8 k each)
            {
                int nn = tid & 127, kq = tid >> 7;
                int kg = k0 + kq * 8;
                const float* wp = &w1[(size_t)(n0 + nn) * NI + kg];
#pragma unroll
                for (int u = 0; u < 8; u++)
                    Bs[kq * 8 + u][nn] = (kg + u < NI) ? wp[u] : 0.f;
            }
            __syncthreads();
#pragma unroll
            for (int k = 0; k < 16; k++) {
                float a[4], bb[8];
                *(float4*)&a[0]  = *(float4*)&As[k][ty * 4];
                *(float4*)&bb[0] = *(float4*)&Bs[k][tx * 8];
                *(float4*)&bb[4] = *(float4*)&Bs[k][tx * 8 + 4];
#pragma unroll
                for (int ii = 0; ii < 4; ii++)
#pragma unroll
                    for (int j = 0; j < 8; j++) acc[ii][j] += a[ii] * bb[j];
            }
            __syncthreads();
        }
#pragma unroll
        for (int ii = 0; ii < 4; ii++) {
            int m = m0 + ty * 4 + ii;
#pragma unroll
            for (int j = 0; j < 8; j++)
                g_XP[(size_t)m * NH + n0 + tx * 8 + j] = acc[ii][j];
        }
        __threadfence();
        __syncthreads();
        if (tid == 0) atomicAdd(&g_ready[p], 1u);   // threshold 8 for p<8
        return;
    }

    if (bid >= 128 && bid < 296) {
        // ---------------- gemmX 128 x 128 tile: m-tiles 8..49 (PRECISION-CRITICAL) ----------------
        float (*As)[129] = (float(*)[129])smraw;
        float (*Bs)[129] = (float(*)[129])(smraw + 16 * 129 * 4);
        int i = bid - 128;
        int p = 8 + (i >> 2);
        int m0 = p * 128, n0 = (i & 3) * 128;
        int tx = tid & 15, ty = tid >> 4;
        float acc[8][8] = {};
        float4 va[2], vb[2];

        auto ldtile = [&](int k0) {
#pragma unroll
            for (int rep = 0; rep < 2; rep++) {
                int f = tid + rep * 256;
                int mm = f >> 2, kq = f & 3;
                int kg = k0 + kq * 4;
                {
                    int m = m0 + mm, t = m >> 6, b = m & 63;
                    const float* xp = &x[((size_t)b * T + t) * NI + kg];
                    float4 v;
                    if (kg + 3 < NI) v = *(const float4*)xp;
                    else {
                        v.x = (kg + 0 < NI) ? xp[0] : 0.f;
                        v.y = (kg + 1 < NI) ? xp[1] : 0.f;
                        v.z = (kg + 2 < NI) ? xp[2] : 0.f;
                        v.w = (kg + 3 < NI) ? xp[3] : 0.f;
                    }
                    va[rep] = v;
                }
                {
                    int n = n0 + mm;
                    const float* wp = &w1[(size_t)n * NI + kg];
                    float4 v;
                    if (kg + 3 < NI) v = *(const float4*)wp;
                    else {
                        v.x = (kg + 0 < NI) ? wp[0] : 0.f;
                        v.y = (kg + 1 < NI) ? wp[1] : 0.f;
                        v.z = (kg + 2 < NI) ? wp[2] : 0.f;
                        v.w = (kg + 3 < NI) ? wp[3] : 0.f;
                    }
                    vb[rep] = v;
                }
            }
        };
        auto sttile = [&]() {
#pragma unroll
            for (int rep = 0; rep < 2; rep++) {
                int f = tid + rep * 256;
                int mm = f >> 2, kq = f & 3;
                As[kq * 4 + 0][mm] = va[rep].x; As[kq * 4 + 1][mm] = va[rep].y;
                As[kq * 4 + 2][mm] = va[rep].z; As[kq * 4 + 3][mm] = va[rep].w;
                Bs[kq * 4 + 0][mm] = vb[rep].x; Bs[kq * 4 + 1][mm] = vb[rep].y;
                Bs[kq * 4 + 2][mm] = vb[rep].z; Bs[kq * 4 + 3][mm] = vb[rep].w;
            }
        };

        ldtile(0);
        for (int k0 = 0; k0 < NI; k0 += 16) {
            sttile();
            __syncthreads();
            if (k0 + 16 < NI) ldtile(k0 + 16);
#pragma unroll
            for (int k = 0; k < 16; k++) {
                float a[8], bb[8];
#pragma unroll
                for (int ii = 0; ii < 4; ii++) {
                    a[ii]      = As[k][ty * 4 + ii];
                    a[4 + ii]  = As[k][64 + ty * 4 + ii];
                    bb[ii]     = Bs[k][tx * 4 + ii];
                    bb[4 + ii] = Bs[k][64 + tx * 4 + ii];
                }
#pragma unroll
                for (int ii = 0; ii < 8; ii++)
#pragma unroll
                    for (int j = 0; j < 8; j++) acc[ii][j] += a[ii] * bb[j];
            }
            __syncthreads();
        }
#pragma unroll
        for (int ii = 0; ii < 8; ii++) {
            int m = m0 + ((ii < 4) ? ty * 4 + ii : 64 + ty * 4 + (ii - 4));
#pragma unroll
            for (int j = 0; j < 8; j++) {
                int n = n0 + ((j < 4) ? tx * 4 + j : 64 + tx * 4 + (j - 4));
                g_XP[(size_t)m * NH + n] = acc[ii][j];
            }
        }
        __threadfence();
        __syncthreads();
        if (tid == 0) atomicAdd(&g_ready[p], 1u);   // threshold 4 for p>=8
        return;
    }

    if (bid >= 296) {
        // ---------------- tin scan ----------------
        int n = (bid - 296) * 256 + tid;
        if (n < B * NI) {
            int b = n / NI, i = n - b * NI;
            float tv = 0.f;
            for (int t = 0; t < T; t++) {
                tv = TAUc * tv + x[(b * T + t) * NI + i];
                g_TIN[((size_t)t * B + b) * NI + i] = tv;
            }
        }
        return;
    }

    // ---------------- forward (+ fused output LIF + reverse filter), bids 0..63 ----------------
    float* ws   = (float*)smraw;            // NO*NH
    float* zsh  = ws + NO * NH;             // NH
    float* errh = zsh + NH;                 // T*NO
    int*   list = (int*)(errh + T * NO);    // NH+64
    unsigned* zmask = (unsigned*)(list + NH + 64);   // 16

    int b = bid;
    int q = tid;
    int lane = tid & 31, w = tid >> 5;
    bool is_n = (tid < 128);
    int ow = w - 4;

    for (int i = tid; i < NO * NH; i += 256) ws[i] = wout[i];
    for (int i = tid; i < NH; i += 256) zsh[i] = 0.f;
    __syncthreads();

    const float4* wrec4 = (const float4*)wrec;
    float4 hm = {0,0,0,0}, tr = {0,0,0,0}, zs = {0,0,0,0};
    float om[5] = {}, os[5] = {};
    int nact = 0, pdone = -1;

    auto do_out = [&](int tp) {
#pragma unroll
        for (int qq = 0; qq < 5; qq++) {
            int o = ow * 5 + qq;
            float s = 0.f;
#pragma unroll
            for (int c = 0; c < 16; c++)
                s += zsh[c * 32 + lane] * ws[o * NH + c * 32 + lane];
#pragma unroll
            for (int off = 16; off; off >>= 1) s += __shfl_xor_sync(0xffffffffu, s, off);
            om[qq] = TAUc * om[qq] * (1.f - os[qq]) + s;
            os[qq] = (om[qq] >= THRc) ? 1.f : 0.f;
            if (lane == 0) {
                out[((size_t)b * T + tp) * NO + o] = os[qq];
                errh[tp * NO + o] = os[qq] - label[((size_t)b * T + tp) * NO + o];
            }
        }
    };

    for (int t = 0; t < T; t++) {
        float4 z = {0,0,0,0};
        unsigned nib = 0;
        if (is_n) {
            int p = t >> 1;
            if (p > pdone) {
                unsigned thr = (p < 8) ? 8u : 4u;
                while (((volatile unsigned*)g_ready)[p] < thr) {}
                pdone = p;
            }
            float4 xp;
            {
                const float4* xp4 = (const float4*)&g_XP[((size_t)t * B + b) * NH] + q;
                xp.x = __ldcg(&xp4->x); xp.y = __ldcg(&xp4->y);
                xp.z = __ldcg(&xp4->z); xp.w = __ldcg(&xp4->w);
            }
            float4 acc = {0,0,0,0};
            for (int i = 0; i < nact; i += 16) {
                float4 v[16];
#pragma unroll
                for (int u = 0; u < 16; u++) {
                    int ix = i + u;
                    float4 zz = {0.f, 0.f, 0.f, 0.f};
                    v[u] = (ix < nact) ? __ldg(&wrec4[(size_t)list[ix] * 128 + q]) : zz;
                }
#pragma unroll
                for (int u = 0; u < 16; u++) {
                    acc.x += v[u].x; acc.y += v[u].y; acc.z += v[u].z; acc.w += v[u].w;
                }
            }
            float4 ht;
            hm.x = TAUc * hm.x * (1.f - zs.x) + xp.x + acc.x;
            hm.y = TAUc * hm.y * (1.f - zs.y) + xp.y + acc.y;
            hm.z = TAUc * hm.z * (1.f - zs.z) + xp.z + acc.z;
            hm.w = TAUc * hm.w * (1.f - zs.w) + xp.w + acc.w;
            z.x = (hm.x >= THRc) ? 1.f : 0.f;
            z.y = (hm.y >= THRc) ? 1.f : 0.f;
            z.z = (hm.z >= THRc) ? 1.f : 0.f;
            z.w = (hm.w >= THRc) ? 1.f : 0.f;
            ht.x = TAUc * fmaxf(0.f, 1.f - fabsf((hm.x - THRc) * (1.f / THRc)));
            ht.y = TAUc * fmaxf(0.f, 1.f - fabsf((hm.y - THRc) * (1.f / THRc)));
            ht.z = TAUc * fmaxf(0.f, 1.f - fabsf((hm.z - THRc) * (1.f / THRc)));
            ht.w = TAUc * fmaxf(0.f, 1.f - fabsf((hm.w - THRc) * (1.f / THRc)));
            tr.x = TAUc * tr.x + zs.x;
            tr.y = TAUc * tr.y + zs.y;
            tr.z = TAUc * tr.z + zs.z;
            tr.w = TAUc * tr.w + zs.w;
            size_t o4 = ((size_t)t * B + b) * 128 + q;
            ((float4*)g_Z)[o4] = z; ((float4*)g_HT)[o4] = ht; ((float4*)g_TREC)[o4] = tr;
            zs = z;

            nib = (z.x != 0.f ? 1u : 0u) | (z.y != 0.f ? 2u : 0u)
                | (z.z != 0.f ? 4u : 0u) | (z.w != 0.f ? 8u : 0u);
            unsigned word = nib << ((lane & 7) * 4);
            word |= __shfl_xor_sync(0xffffffffu, word, 1);
            word |= __shfl_xor_sync(0xffffffffu, word, 2);
            word |= __shfl_xor_sync(0xffffffffu, word, 4);
            if ((lane & 7) == 0) zmask[w * 4 + (lane >> 3)] = word;
        } else if (w >= 4 && t > 0) {
            do_out(t - 1);
        }
        __syncthreads();

        if (is_n) {
            *(float4*)&zsh[4 * q] = z;
            int tot = 0, pre = 0;
            int myc = q >> 3;
#pragma unroll
            for (int c = 0; c < 16; c++) {
                int pc = __popc(zmask[c]);
                if (c < myc) pre += pc;
                tot += pc;
            }
            pre += __popc(zmask[myc] & ((1u << ((q & 7) * 4)) - 1u));
            nact = tot;
            if (nib & 1u) list[pre++] = 4 * q + 0;
            if (nib & 2u) list[pre++] = 4 * q + 1;
            if (nib & 4u) list[pre++] = 4 * q + 2;
            if (nib & 8u) list[pre++] = 4 * q + 3;
        }
        __syncthreads();
    }
    if (!is_n && w >= 4) do_out(T - 1);
    __syncthreads();

    if (tid < NO) {
        float ef = 0.f;
        for (int t = T - 1; t >= 0; t--) {
            ef = errh[t * NO + tid] + KAPc * ef;
            g_EF[((size_t)t * B + b) * NO + tid] = ef;
        }
    }
}

// ---------------- A[m,r] = (EF[m,:] . wout[:,r]) * HT[m,r] ----------------
__global__ void k_A(const float* __restrict__ wout) {
    int gid = blockIdx.x * 256 + threadIdx.x;
    if (gid >= T * B * NH) return;
    int m = gid >> 9;
    int r = gid & (NH - 1);
    const float* ef = g_EF + (size_t)m * NO;
    float L = 0.f;
#pragma unroll
    for (int o = 0; o < NO; o++) L += ef[o] * wout[o * NH + r];
    g_A[gid] = L * g_HT[gid];
}

// ---------------- gemm bodies (device) ----------------
__device__ __forceinline__ void gemm128_body(
    const float* __restrict__ A, int sA,
    const float* __restrict__ Bm, int sB,
    float* __restrict__ C, int N,
    int m0, int n0, int kts, int kte,
    float* __restrict__ As, float* __restrict__ Bs)
{
    int tid = threadIdx.x, tx = tid & 15, ty = tid >> 4;
    float acc[8][8] = {};
    float4 va[2], vb[2];

    auto ldtile = [&](int kt) {
        int k0 = kt * 16;
#pragma unroll
        for (int rep = 0; rep < 2; rep++) {
            int f = tid + rep * 256;
            int kk = f >> 5, c4 = (f & 31) * 4;
            va[rep] = *(const float4*)&A[(size_t)(k0 + kk) * sA + m0 + c4];
            int n = n0 + c4;
            const float* bp = &Bm[(size_t)(k0 + kk) * sB + n];
            float4 bv;
            if (n + 3 < N) bv = *(const float4*)bp;
            else {
                bv.x = (n + 0 < N) ? bp[0] : 0.f;
                bv.y = (n + 1 < N) ? bp[1] : 0.f;
                bv.z = (n + 2 < N) ? bp[2] : 0.f;
                bv.w = (n + 3 < N) ? bp[3] : 0.f;
            }
            vb[rep] = bv;
        }
    };
    auto sttile = [&]() {
#pragma unroll
        for (int rep = 0; rep < 2; rep++) {
            int f = tid + rep * 256;
            int kk = f >> 5, c4 = (f & 31) * 4;
            *(float4*)&As[kk * 128 + c4] = va[rep];
            *(float4*)&Bs[kk * 128 + c4] = vb[rep];
        }
    };

    ldtile(kts);
    for (int kt = kts; kt < kte; kt++) {
        sttile();
        __syncthreads();
        if (kt + 1 < kte) ldtile(kt + 1);
#pragma unroll
        for (int k = 0; k < 16; k++) {
            float a[8], bb[8];
            *(float4*)&a[0]  = *(float4*)&As[k * 128 + ty * 4];
            *(float4*)&a[4]  = *(float4*)&As[k * 128 + 64 + ty * 4];
            *(float4*)&bb[0] = *(float4*)&Bs[k * 128 + tx * 4];
            *(float4*)&bb[4] = *(float4*)&Bs[k * 128 + 64 + tx * 4];
#pragma unroll
            for (int i = 0; i < 8; i++)
#pragma unroll
                for (int j = 0; j < 8; j++) acc[i][j] += a[i] * bb[j];
        }
        __syncthreads();
    }
#pragma unroll
    for (int i = 0; i < 8; i++) {
        int m = m0 + ((i < 4) ? ty * 4 + i : 64 + ty * 4 + (i - 4));
#pragma unroll
        for (int j = 0; j < 8; j++) {
            int n = n0 + ((j < 4) ? tx * 4 + j : 64 + tx * 4 + (j - 4));
            if (n < N) C[(size_t)m * N + n] = acc[i][j];
        }
    }
}

__device__ __forceinline__ void gemm64_body(
    const float* __restrict__ A, int sA,
    const float* __restrict__ Bm, int sB,
    float* __restrict__ C, int M, int N,
    int m0, int n0, int k0s, int k0e,
    float* __restrict__ As, float* __restrict__ Bs)
{
    int tid = threadIdx.x, tx = tid & 15, ty = tid >> 4;
    float acc[4][4] = {};
    for (int k0 = k0s; k0 < k0e; k0 += 16) {
#pragma unroll
        for (int rep = 0; rep < 4; rep++) {
            int e = tid + rep * 256;
            int mm = e & 63, kk = e >> 6;
            int mg = m0 + mm;
            As[kk * 64 + mm] = (mg < M) ? A[(size_t)(k0 + kk) * sA + mg] : 0.f;
            int ng = n0 + mm;
            Bs[kk * 64 + mm] = (ng < N) ? Bm[(size_t)(k0 + kk) * sB + ng] : 0.f;
        }
        __syncthreads();
#pragma unroll
        for (int k = 0; k < 16; k++) {
            float a[4], bb[4];
#pragma unroll
            for (int i = 0; i < 4; i++) a[i]  = As[k * 64 + ty * 4 + i];
#pragma unroll
            for (int j = 0; j < 4; j++) bb[j] = Bs[k * 64 + tx * 4 + j];
#pragma unroll
            for (int i = 0; i < 4; i++)
#pragma unroll
                for (int j = 0; j < 4; j++) acc[i][j] += a[i] * bb[j];
        }
        __syncthreads();
    }
#pragma unroll
    for (int i = 0; i < 4; i++) {
        int m = m0 + ty * 4 + i;
        if (m < M) {
#pragma unroll
            for (int j = 0; j < 4; j++) {
                int n = n0 + tx * 4 + j;
                if (n < N) C[(size_t)m * N + n] = acc[i][j];
            }
        }
    }
}

// ---------------- fused gradients: gf(168) + gr(128) + go(64) = 360 blocks ----------------
__global__ __launch_bounds__(256, 2) void k_grads() {
    __shared__ float As[16 * 128];
    __shared__ float Bs[16 * 128];
    int bid = blockIdx.x;
    if (bid < 168) {
        int z = bid / 24, rem = bid - z * 24;
        int n0 = (rem % 6) * 128, m0 = (rem / 6) * 128;
        const int kst[8] = {0, 57, 114, 171, 228, 285, 342, 400};
        gemm128_body(g_A, NH, g_TIN, NI,
                     g_gp + GFP_OFF + (size_t)z * GF_MN, NI,
                     m0, n0, kst[z], kst[z + 1], As, Bs);
    } else if (bid < 296) {
        int i = bid - 168;
        int z = i / 16, rem = i - z * 16;
        int n0 = (rem % 4) * 128, m0 = (rem / 4) * 128;
        gemm128_body(g_A, NH, g_TREC, NH,
                     g_gp + GRP_OFF + (size_t)z * GR_MN, NH,
                     m0, n0, z * 50, z * 50 + 50, As, Bs);
    } else {
        int i = bid - 296;
        int z = i / 8, nx = i - z * 8;
        gemm64_body(g_EF, NO, g_Z, NH,
                    g_gp + GOP_OFF + (size_t)z * GO_MN, NO, NH,
                    0, nx * 64, z * 800, z * 800 + 800, As, Bs);
    }
}

// ---------------- fused reduce over all three gradient outputs ----------------
__global__ void k_redAll(float* __restrict__ gf, float* __restrict__ gr,
                         float* __restrict__ go) {
    int i = blockIdx.x * 256 + threadIdx.x;
    if (i < GF_MN) {
        float s = 0.f;
#pragma unroll
        for (int z = 0; z < 7; z++) s += g_gp[GFP_OFF + (size_t)z * GF_MN + i];
        gf[i] = LRc * s;
    } else if (i < GF_MN + GR_MN) {
        int j = i - GF_MN;
        float s = 0.f;
#pragma unroll
        for (int z = 0; z < 8; z++) s += g_gp[GRP_OFF + (size_t)z * GR_MN + j];
        gr[j] = LRc * s;
    } else if (i < GF_MN + GR_MN + GO_MN) {
        int j = i - GF_MN - GR_MN;
        float s = 0.f;
#pragma unroll
        for (int z = 0; z < 8; z++) s += g_gp[GOP_OFF + (size_t)z * GO_MN + j];
        go[j] = LRc * s;
    }
}

// ---------------- launch ----------------
extern "C" void kernel_launch(void* const* d_in, const int* in_sizes, int n_in,
                              void* d_out, int out_size) {
    const float* x     = (const float*)d_in[0];
    const float* label = (const float*)d_in[1];
    const float* w1    = (const float*)d_in[3];
    const float* wrec  = (const float*)d_in[4];
    const float* wout  = (const float*)d_in[5];
    float* out = (float*)d_out;
    float* gf = out + B * T * NO;          // [NH, NI]
    float* gr = gf + NH * NI;              // [NH, NH]
    float* go = gr + NH * NH;              // [NO, NH]

    cudaFuncSetAttribute(k_main, cudaFuncAttributeMaxDynamicSharedMemorySize, MAIN_SMEM);

    void* pR;
    cudaGetSymbolAddress(&pR, g_ready);
    cudaMemsetAsync(pR, 0, 64 * sizeof(unsigned));

    k_main<<<471, 256, MAIN_SMEM>>>(x, w1, wrec, wout, label, out);
    k_A<<<(T * B * NH + 255) / 256, 256>>>(wout);
    k_grads<<<360, 256>>>();
    k_redAll<<<(GF_MN + GR_MN + GO_MN + 255) / 256, 256>>>(gf, gr, go);
}

// round 15
// speedup vs baseline: 2.4531x; 1.0761x over previous
#include <cuda_runtime.h>

#define B   64
#define T   100
#define NI  700
#define NH  512
#define NO  20
#define TAUc 0.6f
#define KAPc 0.6f
#define THRc 0.6f
#define LRc  0.05f

// ---------------- persistent device scratch ----------------
__device__ float g_XP  [T*B*NH];   // x @ W1^T, rows m = t*B+b
__device__ float g_TIN [T*B*NI];
__device__ float g_TREC[T*B*NH];
__device__ float g_HT  [T*B*NH];
__device__ float g_Z   [T*B*NH];
__device__ float g_EF  [T*B*NO];
__device__ float g_A   [T*B*NH];
__device__ unsigned g_ready[64];   // per-m-tile XP readiness

// gradient split-K partials: gf 7 parts, gr 8 parts, go 8 parts
#define GF_MN (NH*NI)
#define GR_MN (NH*NH)
#define GO_MN (NO*NH)
#define GFP_OFF 0
#define GRP_OFF (7*GF_MN)
#define GOP_OFF (GRP_OFF + 8*GR_MN)
__device__ float g_gp[GOP_OFF + 8*GO_MN];

#define MAIN_SMEM (13344 * 4)

// ---------------- f32x2 packed-FMA helpers (SASS FFMA2) ----------------
// fma.rn.f32x2 = two independent IEEE fp32 FMAs -> per-lane bitwise identical
// to scalar FFMA chains; only issue count halves.
__device__ __forceinline__ unsigned long long pk2(float x, float y) {
    unsigned long long r;
    asm("mov.b64 %0, {%1, %2};" : "=l"(r) : "f"(x), "f"(y));
    return r;
}
__device__ __forceinline__ void upk2(float& x, float& y, unsigned long long v) {
    asm("mov.b64 {%0, %1}, %2;" : "=f"(x), "=f"(y) : "l"(v));
}
__device__ __forceinline__ void ffma2(unsigned long long& d, unsigned long long a,
                                      unsigned long long b) {
    asm("fma.rn.f32x2 %0, %1, %2, %0;" : "+l"(d) : "l"(a), "l"(b));
}

// ============================================================================
// k_main block map:
//   [0,64)    forward (one sample each) + fused A epilogue
//   [64,128)  gemmX small tiles: m-tiles 0..7 as 64-row tiles
//   [128,296) gemmX 128-row tiles: m-tiles 8..49
//   [296,471) tin scan
// ============================================================================
__global__ __launch_bounds__(256, 2) void k_main(const float* __restrict__ x,
                                                 const float* __restrict__ w1,
                                                 const float* __restrict__ wrec,
                                                 const float* __restrict__ wout,
                                                 const float* __restrict__ label,
                                                 float* __restrict__ out) {
    extern __shared__ char smraw[];
    int bid = blockIdx.x;
    int tid = threadIdx.x;

    if (bid >= 64 && bid < 128) {
        // ---------------- gemmX SMALL tile: 64 x 128, m-tiles 0..7 ----------------
        float (*As)[64]  = (float(*)[64])smraw;
        float (*Bs)[128] = (float(*)[128])(smraw + 16 * 64 * 4);
        int i = bid - 64;
        int p = i >> 3;
        int sub = (i >> 2) & 1;
        int m0 = p * 128 + sub * 64;
        int n0 = (i & 3) * 128;
        int tx = tid & 15, ty = tid >> 4;
        unsigned long long acc2[4][4];
#pragma unroll
        for (int ii = 0; ii < 4; ii++)
#pragma unroll
            for (int jj = 0; jj < 4; jj++) acc2[ii][jj] = 0ull;

        for (int k0 = 0; k0 < NI; k0 += 16) {
            {
                int mm = tid & 63, kq = tid >> 6;
                int kg = k0 + kq * 4;
                int m = m0 + mm, t = m >> 6, b = m & 63;
                const float* xp = &x[((size_t)b * T + t) * NI + kg];
                float4 v;
                if (kg + 3 < NI) v = *(const float4*)xp;
                else {
                    v.x = (kg + 0 < NI) ? xp[0] : 0.f;
                    v.y = (kg + 1 < NI) ? xp[1] : 0.f;
                    v.z = (kg + 2 < NI) ? xp[2] : 0.f;
                    v.w = (kg + 3 < NI) ? xp[3] : 0.f;
                }
                As[kq * 4 + 0][mm] = v.x; As[kq * 4 + 1][mm] = v.y;
                As[kq * 4 + 2][mm] = v.z; As[kq * 4 + 3][mm] = v.w;
            }
            {
                int nn = tid & 127, kq = tid >> 7;
                int kg = k0 + kq * 8;
                const float* wp = &w1[(size_t)(n0 + nn) * NI + kg];
#pragma unroll
                for (int u = 0; u < 8; u++)
                    Bs[kq * 8 + u][nn] = (kg + u < NI) ? wp[u] : 0.f;
            }
            __syncthreads();
#pragma unroll
            for (int k = 0; k < 16; k++) {
                float a[4], bb[8];
                *(float4*)&a[0]  = *(float4*)&As[k][ty * 4];
                *(float4*)&bb[0] = *(float4*)&Bs[k][tx * 8];
                *(float4*)&bb[4] = *(float4*)&Bs[k][tx * 8 + 4];
                unsigned long long b2[4];
#pragma unroll
                for (int jj = 0; jj < 4; jj++) b2[jj] = pk2(bb[2 * jj], bb[2 * jj + 1]);
#pragma unroll
                for (int ii = 0; ii < 4; ii++) {
                    unsigned long long a2 = pk2(a[ii], a[ii]);
#pragma unroll
                    for (int jj = 0; jj < 4; jj++) ffma2(acc2[ii][jj], a2, b2[jj]);
                }
            }
            __syncthreads();
        }
#pragma unroll
        for (int ii = 0; ii < 4; ii++) {
            int m = m0 + ty * 4 + ii;
            float av[8];
#pragma unroll
            for (int jj = 0; jj < 4; jj++) upk2(av[2 * jj], av[2 * jj + 1], acc2[ii][jj]);
#pragma unroll
            for (int j = 0; j < 8; j++)
                g_XP[(size_t)m * NH + n0 + tx * 8 + j] = av[j];
        }
        __threadfence();
        __syncthreads();
        if (tid == 0) atomicAdd(&g_ready[p], 1u);
        return;
    }

    if (bid >= 128 && bid < 296) {
        // ---------------- gemmX 128 x 128 tile: m-tiles 8..49 ----------------
        float (*As)[129] = (float(*)[129])smraw;
        float (*Bs)[129] = (float(*)[129])(smraw + 16 * 129 * 4);
        int i = bid - 128;
        int p = 8 + (i >> 2);
        int m0 = p * 128, n0 = (i & 3) * 128;
        int tx = tid & 15, ty = tid >> 4;
        unsigned long long acc2[8][4];
#pragma unroll
        for (int ii = 0; ii < 8; ii++)
#pragma unroll
            for (int jj = 0; jj < 4; jj++) acc2[ii][jj] = 0ull;
        float4 va[2], vb[2];

        auto ldtile = [&](int k0) {
#pragma unroll
            for (int rep = 0; rep < 2; rep++) {
                int f = tid + rep * 256;
                int mm = f >> 2, kq = f & 3;
                int kg = k0 + kq * 4;
                {
                    int m = m0 + mm, t = m >> 6, b = m & 63;
                    const float* xp = &x[((size_t)b * T + t) * NI + kg];
                    float4 v;
                    if (kg + 3 < NI) v = *(const float4*)xp;
                    else {
                        v.x = (kg + 0 < NI) ? xp[0] : 0.f;
                        v.y = (kg + 1 < NI) ? xp[1] : 0.f;
                        v.z = (kg + 2 < NI) ? xp[2] : 0.f;
                        v.w = (kg + 3 < NI) ? xp[3] : 0.f;
                    }
                    va[rep] = v;
                }
                {
                    int n = n0 + mm;
                    const float* wp = &w1[(size_t)n * NI + kg];
                    float4 v;
                    if (kg + 3 < NI) v = *(const float4*)wp;
                    else {
                        v.x = (kg + 0 < NI) ? wp[0] : 0.f;
                        v.y = (kg + 1 < NI) ? wp[1] : 0.f;
                        v.z = (kg + 2 < NI) ? wp[2] : 0.f;
                        v.w = (kg + 3 < NI) ? wp[3] : 0.f;
                    }
                    vb[rep] = v;
                }
            }
        };
        auto sttile = [&]() {
#pragma unroll
            for (int rep = 0; rep < 2; rep++) {
                int f = tid + rep * 256;
                int mm = f >> 2, kq = f & 3;
                As[kq * 4 + 0][mm] = va[rep].x; As[kq * 4 + 1][mm] = va[rep].y;
                As[kq * 4 + 2][mm] = va[rep].z; As[kq * 4 + 3][mm] = va[rep].w;
                Bs[kq * 4 + 0][mm] = vb[rep].x; Bs[kq * 4 + 1][mm] = vb[rep].y;
                Bs[kq * 4 + 2][mm] = vb[rep].z; Bs[kq * 4 + 3][mm] = vb[rep].w;
            }
        };

        ldtile(0);
        for (int k0 = 0; k0 < NI; k0 += 16) {
            sttile();
            __syncthreads();
            if (k0 + 16 < NI) ldtile(k0 + 16);
#pragma unroll
            for (int k = 0; k < 16; k++) {
                float a[8], bb[8];
#pragma unroll
                for (int ii = 0; ii < 4; ii++) {
                    a[ii]      = As[k][ty * 4 + ii];
                    a[4 + ii]  = As[k][64 + ty * 4 + ii];
                    bb[ii]     = Bs[k][tx * 4 + ii];
                    bb[4 + ii] = Bs[k][64 + tx * 4 + ii];
                }
                unsigned long long b2[4];
#pragma unroll
                for (int jj = 0; jj < 4; jj++) b2[jj] = pk2(bb[2 * jj], bb[2 * jj + 1]);
#pragma unroll
                for (int ii = 0; ii < 8; ii++) {
                    unsigned long long a2 = pk2(a[ii], a[ii]);
#pragma unroll
                    for (int jj = 0; jj < 4; jj++) ffma2(acc2[ii][jj], a2, b2[jj]);
                }
            }
            __syncthreads();
        }
#pragma unroll
        for (int ii = 0; ii < 8; ii++) {
            int m = m0 + ((ii < 4) ? ty * 4 + ii : 64 + ty * 4 + (ii - 4));
            float av[8];
#pragma unroll
            for (int jj = 0; jj < 4; jj++) upk2(av[2 * jj], av[2 * jj + 1], acc2[ii][jj]);
#pragma unroll
            for (int j = 0; j < 8; j++) {
                int n = n0 + ((j < 4) ? tx * 4 + j : 64 + tx * 4 + (j - 4));
                g_XP[(size_t)m * NH + n] = av[j];
            }
        }
        __threadfence();
        __syncthreads();
        if (tid == 0) atomicAdd(&g_ready[p], 1u);
        return;
    }

    if (bid >= 296) {
        // ---------------- tin scan ----------------
        int n = (bid - 296) * 256 + tid;
        if (n < B * NI) {
            int b = n / NI, i = n - b * NI;
            float tv = 0.f;
            for (int t = 0; t < T; t++) {
                tv = TAUc * tv + x[(b * T + t) * NI + i];
                g_TIN[((size_t)t * B + b) * NI + i] = tv;
            }
        }
        return;
    }

    // ---------------- forward (+ output LIF + reverse filter + fused A), bids 0..63 ----------------
    float* ws   = (float*)smraw;            // NO*NH
    float* zsh  = ws + NO * NH;             // NH
    float* errh = zsh + NH;                 // T*NO (err, then EF in place)
    int*   list = (int*)(errh + T * NO);    // NH+64
    unsigned* zmask = (unsigned*)(list + NH + 64);   // 16

    int b = bid;
    int q = tid;
    int lane = tid & 31, w = tid >> 5;
    bool is_n = (tid < 128);
    int ow = w - 4;

    for (int i = tid; i < NO * NH; i += 256) ws[i] = wout[i];
    for (int i = tid; i < NH; i += 256) zsh[i] = 0.f;
    __syncthreads();

    const float4* wrec4 = (const float4*)wrec;
    float4 hm = {0,0,0,0}, tr = {0,0,0,0}, zs = {0,0,0,0};
    float om[5] = {}, os[5] = {};
    int nact = 0, pdone = -1;

    auto do_out = [&](int tp) {
#pragma unroll
        for (int qq = 0; qq < 5; qq++) {
            int o = ow * 5 + qq;
            float s = 0.f;
#pragma unroll
            for (int c = 0; c < 16; c++)
                s += zsh[c * 32 + lane] * ws[o * NH + c * 32 + lane];
#pragma unroll
            for (int off = 16; off; off >>= 1) s += __shfl_xor_sync(0xffffffffu, s, off);
            om[qq] = TAUc * om[qq] * (1.f - os[qq]) + s;
            os[qq] = (om[qq] >= THRc) ? 1.f : 0.f;
            if (lane == 0) {
                out[((size_t)b * T + tp) * NO + o] = os[qq];
                errh[tp * NO + o] = os[qq] - label[((size_t)b * T + tp) * NO + o];
            }
        }
    };

    for (int t = 0; t < T; t++) {
        float4 z = {0,0,0,0};
        unsigned nib = 0;
        if (is_n) {
            int p = t >> 1;
            if (p > pdone) {
                unsigned thr = (p < 8) ? 8u : 4u;
                while (((volatile unsigned*)g_ready)[p] < thr) {}
                pdone = p;
            }
            float4 xp;
            {
                const float4* xp4 = (const float4*)&g_XP[((size_t)t * B + b) * NH] + q;
                xp.x = __ldcg(&xp4->x); xp.y = __ldcg(&xp4->y);
                xp.z = __ldcg(&xp4->z); xp.w = __ldcg(&xp4->w);
            }
            float4 acc = {0,0,0,0};
            for (int i = 0; i < nact; i += 16) {
                float4 v[16];
#pragma unroll
                for (int u = 0; u < 16; u++) {
                    int ix = i + u;
                    float4 zz = {0.f, 0.f, 0.f, 0.f};
                    v[u] = (ix < nact) ? __ldg(&wrec4[(size_t)list[ix] * 128 + q]) : zz;
                }
#pragma unroll
                for (int u = 0; u < 16; u++) {
                    acc.x += v[u].x; acc.y += v[u].y; acc.z += v[u].z; acc.w += v[u].w;
                }
            }
            float4 ht;
            hm.x = TAUc * hm.x * (1.f - zs.x) + xp.x + acc.x;
            hm.y = TAUc * hm.y * (1.f - zs.y) + xp.y + acc.y;
            hm.z = TAUc * hm.z * (1.f - zs.z) + xp.z + acc.z;
            hm.w = TAUc * hm.w * (1.f - zs.w) + xp.w + acc.w;
            z.x = (hm.x >= THRc) ? 1.f : 0.f;
            z.y = (hm.y >= THRc) ? 1.f : 0.f;
            z.z = (hm.z >= THRc) ? 1.f : 0.f;
            z.w = (hm.w >= THRc) ? 1.f : 0.f;
            ht.x = TAUc * fmaxf(0.f, 1.f - fabsf((hm.x - THRc) * (1.f / THRc)));
            ht.y = TAUc * fmaxf(0.f, 1.f - fabsf((hm.y - THRc) * (1.f / THRc)));
            ht.z = TAUc * fmaxf(0.f, 1.f - fabsf((hm.z - THRc) * (1.f / THRc)));
            ht.w = TAUc * fmaxf(0.f, 1.f - fabsf((hm.w - THRc) * (1.f / THRc)));
            tr.x = TAUc * tr.x + zs.x;
            tr.y = TAUc * tr.y + zs.y;
            tr.z = TAUc * tr.z + zs.z;
            tr.w = TAUc * tr.w + zs.w;
            size_t o4 = ((size_t)t * B + b) * 128 + q;
            ((float4*)g_Z)[o4] = z; ((float4*)g_HT)[o4] = ht; ((float4*)g_TREC)[o4] = tr;
            zs = z;

            nib = (z.x != 0.f ? 1u : 0u) | (z.y != 0.f ? 2u : 0u)
                | (z.z != 0.f ? 4u : 0u) | (z.w != 0.f ? 8u : 0u);
            unsigned word = nib << ((lane & 7) * 4);
            word |= __shfl_xor_sync(0xffffffffu, word, 1);
            word |= __shfl_xor_sync(0xffffffffu, word, 2);
            word |= __shfl_xor_sync(0xffffffffu, word, 4);
            if ((lane & 7) == 0) zmask[w * 4 + (lane >> 3)] = word;
        } else if (w >= 4 && t > 0) {
            do_out(t - 1);
        }
        __syncthreads();

        if (is_n) {
            *(float4*)&zsh[4 * q] = z;
            int tot = 0, pre = 0;
            int myc = q >> 3;
#pragma unroll
            for (int c = 0; c < 16; c++) {
                int pc = __popc(zmask[c]);
                if (c < myc) pre += pc;
                tot += pc;
            }
            pre += __popc(zmask[myc] & ((1u << ((q & 7) * 4)) - 1u));
            nact = tot;
            if (nib & 1u) list[pre++] = 4 * q + 0;
            if (nib & 2u) list[pre++] = 4 * q + 1;
            if (nib & 4u) list[pre++] = 4 * q + 2;
            if (nib & 8u) list[pre++] = 4 * q + 3;
        }
        __syncthreads();
    }
    if (!is_n && w >= 4) do_out(T - 1);
    __syncthreads();

    // reverse kappa filter (EF written to errh in place + g_EF)
    if (tid < NO) {
        float ef = 0.f;
        for (int t = T - 1; t >= 0; t--) {
            ef = errh[t * NO + tid] + KAPc * ef;
            errh[t * NO + tid] = ef;
            g_EF[((size_t)t * B + b) * NO + tid] = ef;
        }
    }
    __syncthreads();

    // fused A: A[t*B+b, r] = (EF[t,:] . wout[:,r]) * HT[t*B+b, r]
    for (int e = tid; e < T * NH; e += 256) {
        int t = e >> 9, r = e & (NH - 1);
        const float* ef = errh + t * NO;
        float L = 0.f;
#pragma unroll
        for (int o = 0; o < NO; o++) L += ef[o] * ws[o * NH + r];
        size_t m = (size_t)t * B + b;
        g_A[m * NH + r] = L * g_HT[m * NH + r];
    }
}

// ---------------- gemm bodies (device) ----------------
__device__ __forceinline__ void gemm128_body(
    const float* __restrict__ A, int sA,
    const float* __restrict__ Bm, int sB,
    float* __restrict__ C, int N,
    int m0, int n0, int kts, int kte,
    float* __restrict__ As, float* __restrict__ Bs)
{
    int tid = threadIdx.x, tx = tid & 15, ty = tid >> 4;
    unsigned long long acc2[8][4];
#pragma unroll
    for (int ii = 0; ii < 8; ii++)
#pragma unroll
        for (int jj = 0; jj < 4; jj++) acc2[ii][jj] = 0ull;
    float4 va[2], vb[2];

    auto ldtile = [&](int kt) {
        int k0 = kt * 16;
#pragma unroll
        for (int rep = 0; rep < 2; rep++) {
            int f = tid + rep * 256;
            int kk = f >> 5, c4 = (f & 31) * 4;
            va[rep] = *(const float4*)&A[(size_t)(k0 + kk) * sA + m0 + c4];
            int n = n0 + c4;
            const float* bp = &Bm[(size_t)(k0 + kk) * sB + n];
            float4 bv;
            if (n + 3 < N) bv = *(const float4*)bp;
            else {
                bv.x = (n + 0 < N) ? bp[0] : 0.f;
                bv.y = (n + 1 < N) ? bp[1] : 0.f;
                bv.z = (n + 2 < N) ? bp[2] : 0.f;
                bv.w = (n + 3 < N) ? bp[3] : 0.f;
            }
            vb[rep] = bv;
        }
    };
    auto sttile = [&]() {
#pragma unroll
        for (int rep = 0; rep < 2; rep++) {
            int f = tid + rep * 256;
            int kk = f >> 5, c4 = (f & 31) * 4;
            *(float4*)&As[kk * 128 + c4] = va[rep];
            *(float4*)&Bs[kk * 128 + c4] = vb[rep];
        }
    };

    ldtile(kts);
    for (int kt = kts; kt < kte; kt++) {
        sttile();
        __syncthreads();
        if (kt + 1 < kte) ldtile(kt + 1);
#pragma unroll
        for (int k = 0; k < 16; k++) {
            float a[8], bb[8];
            *(float4*)&a[0]  = *(float4*)&As[k * 128 + ty * 4];
            *(float4*)&a[4]  = *(float4*)&As[k * 128 + 64 + ty * 4];
            *(float4*)&bb[0] = *(float4*)&Bs[k * 128 + tx * 4];
            *(float4*)&bb[4] = *(float4*)&Bs[k * 128 + 64 + tx * 4];
            unsigned long long b2[4];
#pragma unroll
            for (int jj = 0; jj < 4; jj++) b2[jj] = pk2(bb[2 * jj], bb[2 * jj + 1]);
#pragma unroll
            for (int ii = 0; ii < 8; ii++) {
                unsigned long long a2 = pk2(a[ii], a[ii]);
#pragma unroll
                for (int jj = 0; jj < 4; jj++) ffma2(acc2[ii][jj], a2, b2[jj]);
            }
        }
        __syncthreads();
    }
#pragma unroll
    for (int ii = 0; ii < 8; ii++) {
        int m = m0 + ((ii < 4) ? ty * 4 + ii : 64 + ty * 4 + (ii - 4));
        float av[8];
#pragma unroll
        for (int jj = 0; jj < 4; jj++) upk2(av[2 * jj], av[2 * jj + 1], acc2[ii][jj]);
#pragma unroll
        for (int j = 0; j < 8; j++) {
            int n = n0 + ((j < 4) ? tx * 4 + j : 64 + tx * 4 + (j - 4));
            if (n < N) C[(size_t)m * N + n] = av[j];
        }
    }
}

__device__ __forceinline__ void gemm64_body(
    const float* __restrict__ A, int sA,
    const float* __restrict__ Bm, int sB,
    float* __restrict__ C, int M, int N,
    int m0, int n0, int k0s, int k0e,
    float* __restrict__ As, float* __restrict__ Bs)
{
    int tid = threadIdx.x, tx = tid & 15, ty = tid >> 4;
    float acc[4][4] = {};
    for (int k0 = k0s; k0 < k0e; k0 += 16) {
#pragma unroll
        for (int rep = 0; rep < 4; rep++) {
            int e = tid + rep * 256;
            int mm = e & 63, kk = e >> 6;
            int mg = m0 + mm;
            As[kk * 64 + mm] = (mg < M) ? A[(size_t)(k0 + kk) * sA + mg] : 0.f;
            int ng = n0 + mm;
            Bs[kk * 64 + mm] = (ng < N) ? Bm[(size_t)(k0 + kk) * sB + ng] : 0.f;
        }
        __syncthreads();
#pragma unroll
        for (int k = 0; k < 16; k++) {
            float a[4], bb[4];
#pragma unroll
            for (int i = 0; i < 4; i++) a[i]  = As[k * 64 + ty * 4 + i];
#pragma unroll
            for (int j = 0; j < 4; j++) bb[j] = Bs[k * 64 + tx * 4 + j];
#pragma unroll
            for (int i = 0; i < 4; i++)
#pragma unroll
                for (int j = 0; j < 4; j++) acc[i][j] += a[i] * bb[j];
        }
        __syncthreads();
    }
#pragma unroll
    for (int i = 0; i < 4; i++) {
        int m = m0 + ty * 4 + i;
        if (m < M) {
#pragma unroll
            for (int j = 0; j < 4; j++) {
                int n = n0 + tx * 4 + j;
                if (n < N) C[(size_t)m * N + n] = acc[i][j];
            }
        }
    }
}

// ---------------- fused gradients: gf(168) + gr(128) + go(64) = 360 blocks ----------------
__global__ __launch_bounds__(256, 2) void k_grads() {
    __shared__ float As[16 * 128];
    __shared__ float Bs[16 * 128];
    int bid = blockIdx.x;
    if (bid < 168) {
        int z = bid / 24, rem = bid - z * 24;
        int n0 = (rem % 6) * 128, m0 = (rem / 6) * 128;
        const int kst[8] = {0, 57, 114, 171, 228, 285, 342, 400};
        gemm128_body(g_A, NH, g_TIN, NI,
                     g_gp + GFP_OFF + (size_t)z * GF_MN, NI,
                     m0, n0, kst[z], kst[z + 1], As, Bs);
    } else if (bid < 296) {
        int i = bid - 168;
        int z = i / 16, rem = i - z * 16;
        int n0 = (rem % 4) * 128, m0 = (rem / 4) * 128;
        gemm128_body(g_A, NH, g_TREC, NH,
                     g_gp + GRP_OFF + (size_t)z * GR_MN, NH,
                     m0, n0, z * 50, z * 50 + 50, As, Bs);
    } else {
        int i = bid - 296;
        int z = i / 8, nx = i - z * 8;
        gemm64_body(g_EF, NO, g_Z, NH,
                    g_gp + GOP_OFF + (size_t)z * GO_MN, NO, NH,
                    0, nx * 64, z * 800, z * 800 + 800, As, Bs);
    }
}

// ---------------- fused reduce over all three gradient outputs ----------------
__global__ void k_redAll(float* __restrict__ gf, float* __restrict__ gr,
                         float* __restrict__ go) {
    int i = blockIdx.x * 256 + threadIdx.x;
    if (i < GF_MN) {
        float s = 0.f;
#pragma unroll
        for (int z = 0; z < 7; z++) s += g_gp[GFP_OFF + (size_t)z * GF_MN + i];
        gf[i] = LRc * s;
    } else if (i < GF_MN + GR_MN) {
        int j = i - GF_MN;
        float s = 0.f;
#pragma unroll
        for (int z = 0; z < 8; z++) s += g_gp[GRP_OFF + (size_t)z * GR_MN + j];
        gr[j] = LRc * s;
    } else if (i < GF_MN + GR_MN + GO_MN) {
        int j = i - GF_MN - GR_MN;
        float s = 0.f;
#pragma unroll
        for (int z = 0; z < 8; z++) s += g_gp[GOP_OFF + (size_t)z * GO_MN + j];
        go[j] = LRc * s;
    }
}

// ---------------- launch ----------------
extern "C" void kernel_launch(void* const* d_in, const int* in_sizes, int n_in,
                              void* d_out, int out_size) {
    const float* x     = (const float*)d_in[0];
    const float* label = (const float*)d_in[1];
    const float* w1    = (const float*)d_in[3];
    const float* wrec  = (const float*)d_in[4];
    const float* wout  = (const float*)d_in[5];
    float* out = (float*)d_out;
    float* gf = out + B * T * NO;          // [NH, NI]
    float* gr = gf + NH * NI;              // [NH, NH]
    float* go = gr + NH * NH;              // [NO, NH]

    cudaFuncSetAttribute(k_main, cudaFuncAttributeMaxDynamicSharedMemorySize, MAIN_SMEM);

    void* pR;
    cudaGetSymbolAddress(&pR, g_ready);
    cudaMemsetAsync(pR, 0, 64 * sizeof(unsigned));

    k_main<<<471, 256, MAIN_SMEM>>>(x, w1, wrec, wout, label, out);
    k_grads<<<360, 256>>>();
    k_redAll<<<(GF_MN + GR_MN + GO_MN + 255) / 256, 256>>>(gf, gr, go);
}

// round 16
// speedup vs baseline: 2.4686x; 1.0063x over previous
#include <cuda_runtime.h>

#define B   64
#define T   100
#define NI  700
#define NH  512
#define NO  20
#define TAUc 0.6f
#define KAPc 0.6f
#define THRc 0.6f
#define LRc  0.05f

// ---------------- persistent device scratch ----------------
__device__ float g_XP  [T*B*NH];   // x @ W1^T, rows m = t*B+b
__device__ float g_TIN [T*B*NI];
__device__ float g_TREC[T*B*NH];
__device__ float g_HT  [T*B*NH];
__device__ float g_Z   [T*B*NH];
__device__ float g_EF  [T*B*NO];
__device__ float g_A   [T*B*NH];
__device__ unsigned g_ready[64];   // per-m-tile XP readiness

// gradient split-K partials: gf 7 parts, gr 8 parts, go 8 parts
#define GF_MN (NH*NI)
#define GR_MN (NH*NH)
#define GO_MN (NO*NH)
#define GFP_OFF 0
#define GRP_OFF (7*GF_MN)
#define GOP_OFF (GRP_OFF + 8*GR_MN)
__device__ float g_gp[GOP_OFF + 8*GO_MN];

#define MAIN_SMEM (13344 * 4)

// ---------------- f32x2 packed helpers (SASS FFMA2/FADD2) ----------------
// Per-lane IEEE-identical to scalar chains; only issue count halves.
__device__ __forceinline__ unsigned long long pk2(float x, float y) {
    unsigned long long r;
    asm("mov.b64 %0, {%1, %2};" : "=l"(r) : "f"(x), "f"(y));
    return r;
}
__device__ __forceinline__ void upk2(float& x, float& y, unsigned long long v) {
    asm("mov.b64 {%0, %1}, %2;" : "=f"(x), "=f"(y) : "l"(v));
}
__device__ __forceinline__ void ffma2(unsigned long long& d, unsigned long long a,
                                      unsigned long long b) {
    asm("fma.rn.f32x2 %0, %1, %2, %0;" : "+l"(d) : "l"(a), "l"(b));
}
__device__ __forceinline__ void fadd2(unsigned long long& d, unsigned long long a) {
    asm("add.rn.f32x2 %0, %0, %1;" : "+l"(d) : "l"(a));
}

// ============================================================================
// k_main block map:
//   [0,64)    forward (one sample each) + fused A epilogue
//   [64,128)  gemmX small tiles: m-tiles 0..7 as 64-row tiles
//   [128,296) gemmX 128-row tiles: m-tiles 8..49
//   [296,471) tin scan
// ============================================================================
__global__ __launch_bounds__(256, 2) void k_main(const float* __restrict__ x,
                                                 const float* __restrict__ w1,
                                                 const float* __restrict__ wrec,
                                                 const float* __restrict__ wout,
                                                 const float* __restrict__ label,
                                                 float* __restrict__ out) {
    extern __shared__ char smraw[];
    int bid = blockIdx.x;
    int tid = threadIdx.x;

    if (bid >= 64 && bid < 128) {
        // ---------------- gemmX SMALL tile: 64 x 128, m-tiles 0..7 ----------------
        float (*As)[64]  = (float(*)[64])smraw;
        float (*Bs)[128] = (float(*)[128])(smraw + 16 * 64 * 4);
        int i = bid - 64;
        int p = i >> 3;
        int sub = (i >> 2) & 1;
        int m0 = p * 128 + sub * 64;
        int n0 = (i & 3) * 128;
        int tx = tid & 15, ty = tid >> 4;
        unsigned long long acc2[4][4];
#pragma unroll
        for (int ii = 0; ii < 4; ii++)
#pragma unroll
            for (int jj = 0; jj < 4; jj++) acc2[ii][jj] = 0ull;

        for (int k0 = 0; k0 < NI; k0 += 16) {
            {
                int mm = tid & 63, kq = tid >> 6;
                int kg = k0 + kq * 4;
                int m = m0 + mm, t = m >> 6, b = m & 63;
                const float* xp = &x[((size_t)b * T + t) * NI + kg];
                float4 v;
                if (kg + 3 < NI) v = *(const float4*)xp;
                else {
                    v.x = (kg + 0 < NI) ? xp[0] : 0.f;
                    v.y = (kg + 1 < NI) ? xp[1] : 0.f;
                    v.z = (kg + 2 < NI) ? xp[2] : 0.f;
                    v.w = (kg + 3 < NI) ? xp[3] : 0.f;
                }
                As[kq * 4 + 0][mm] = v.x; As[kq * 4 + 1][mm] = v.y;
                As[kq * 4 + 2][mm] = v.z; As[kq * 4 + 3][mm] = v.w;
            }
            {
                int nn = tid & 127, kq = tid >> 7;
                int kg = k0 + kq * 8;
                const float* wp = &w1[(size_t)(n0 + nn) * NI + kg];
#pragma unroll
                for (int u = 0; u < 8; u++)
                    Bs[kq * 8 + u][nn] = (kg + u < NI) ? wp[u] : 0.f;
            }
            __syncthreads();
#pragma unroll
            for (int k = 0; k < 16; k++) {
                float a[4], bb[8];
                *(float4*)&a[0]  = *(float4*)&As[k][ty * 4];
                *(float4*)&bb[0] = *(float4*)&Bs[k][tx * 8];
                *(float4*)&bb[4] = *(float4*)&Bs[k][tx * 8 + 4];
                unsigned long long b2[4];
#pragma unroll
                for (int jj = 0; jj < 4; jj++) b2[jj] = pk2(bb[2 * jj], bb[2 * jj + 1]);
#pragma unroll
                for (int ii = 0; ii < 4; ii++) {
                    unsigned long long a2 = pk2(a[ii], a[ii]);
#pragma unroll
                    for (int jj = 0; jj < 4; jj++) ffma2(acc2[ii][jj], a2, b2[jj]);
                }
            }
            __syncthreads();
        }
#pragma unroll
        for (int ii = 0; ii < 4; ii++) {
            int m = m0 + ty * 4 + ii;
            float av[8];
#pragma unroll
            for (int jj = 0; jj < 4; jj++) upk2(av[2 * jj], av[2 * jj + 1], acc2[ii][jj]);
#pragma unroll
            for (int j = 0; j < 8; j++)
                g_XP[(size_t)m * NH + n0 + tx * 8 + j] = av[j];
        }
        __threadfence();
        __syncthreads();
        if (tid == 0) atomicAdd(&g_ready[p], 1u);
        return;
    }

    if (bid >= 128 && bid < 296) {
        // ---------------- gemmX 128 x 128 tile: m-tiles 8..49 ----------------
        float (*As)[129] = (float(*)[129])smraw;
        float (*Bs)[129] = (float(*)[129])(smraw + 16 * 129 * 4);
        int i = bid - 128;
        int p = 8 + (i >> 2);
        int m0 = p * 128, n0 = (i & 3) * 128;
        int tx = tid & 15, ty = tid >> 4;
        unsigned long long acc2[8][4];
#pragma unroll
        for (int ii = 0; ii < 8; ii++)
#pragma unroll
            for (int jj = 0; jj < 4; jj++) acc2[ii][jj] = 0ull;
        float4 va[2], vb[2];

        auto ldtile = [&](int k0) {
#pragma unroll
            for (int rep = 0; rep < 2; rep++) {
                int f = tid + rep * 256;
                int mm = f >> 2, kq = f & 3;
                int kg = k0 + kq * 4;
                {
                    int m = m0 + mm, t = m >> 6, b = m & 63;
                    const float* xp = &x[((size_t)b * T + t) * NI + kg];
                    float4 v;
                    if (kg + 3 < NI) v = *(const float4*)xp;
                    else {
                        v.x = (kg + 0 < NI) ? xp[0] : 0.f;
                        v.y = (kg + 1 < NI) ? xp[1] : 0.f;
                        v.z = (kg + 2 < NI) ? xp[2] : 0.f;
                        v.w = (kg + 3 < NI) ? xp[3] : 0.f;
                    }
                    va[rep] = v;
                }
                {
                    int n = n0 + mm;
                    const float* wp = &w1[(size_t)n * NI + kg];
                    float4 v;
                    if (kg + 3 < NI) v = *(const float4*)wp;
                    else {
                        v.x = (kg + 0 < NI) ? wp[0] : 0.f;
                        v.y = (kg + 1 < NI) ? wp[1] : 0.f;
                        v.z = (kg + 2 < NI) ? wp[2] : 0.f;
                        v.w = (kg + 3 < NI) ? wp[3] : 0.f;
                    }
                    vb[rep] = v;
                }
            }
        };
        auto sttile = [&]() {
#pragma unroll
            for (int rep = 0; rep < 2; rep++) {
                int f = tid + rep * 256;
                int mm = f >> 2, kq = f & 3;
                As[kq * 4 + 0][mm] = va[rep].x; As[kq * 4 + 1][mm] = va[rep].y;
                As[kq * 4 + 2][mm] = va[rep].z; As[kq * 4 + 3][mm] = va[rep].w;
                Bs[kq * 4 + 0][mm] = vb[rep].x; Bs[kq * 4 + 1][mm] = vb[rep].y;
                Bs[kq * 4 + 2][mm] = vb[rep].z; Bs[kq * 4 + 3][mm] = vb[rep].w;
            }
        };

        ldtile(0);
        for (int k0 = 0; k0 < NI; k0 += 16) {
            sttile();
            __syncthreads();
            if (k0 + 16 < NI) ldtile(k0 + 16);
#pragma unroll
            for (int k = 0; k < 16; k++) {
                float a[8], bb[8];
#pragma unroll
                for (int ii = 0; ii < 4; ii++) {
                    a[ii]      = As[k][ty * 4 + ii];
                    a[4 + ii]  = As[k][64 + ty * 4 + ii];
                    bb[ii]     = Bs[k][tx * 4 + ii];
                    bb[4 + ii] = Bs[k][64 + tx * 4 + ii];
                }
                unsigned long long b2[4];
#pragma unroll
                for (int jj = 0; jj < 4; jj++) b2[jj] = pk2(bb[2 * jj], bb[2 * jj + 1]);
#pragma unroll
                for (int ii = 0; ii < 8; ii++) {
                    unsigned long long a2 = pk2(a[ii], a[ii]);
#pragma unroll
                    for (int jj = 0; jj < 4; jj++) ffma2(acc2[ii][jj], a2, b2[jj]);
                }
            }
            __syncthreads();
        }
#pragma unroll
        for (int ii = 0; ii < 8; ii++) {
            int m = m0 + ((ii < 4) ? ty * 4 + ii : 64 + ty * 4 + (ii - 4));
            float av[8];
#pragma unroll
            for (int jj = 0; jj < 4; jj++) upk2(av[2 * jj], av[2 * jj + 1], acc2[ii][jj]);
#pragma unroll
            for (int j = 0; j < 8; j++) {
                int n = n0 + ((j < 4) ? tx * 4 + j : 64 + tx * 4 + (j - 4));
                g_XP[(size_t)m * NH + n] = av[j];
            }
        }
        __threadfence();
        __syncthreads();
        if (tid == 0) atomicAdd(&g_ready[p], 1u);
        return;
    }

    if (bid >= 296) {
        // ---------------- tin scan ----------------
        int n = (bid - 296) * 256 + tid;
        if (n < B * NI) {
            int b = n / NI, i = n - b * NI;
            float tv = 0.f;
            for (int t = 0; t < T; t++) {
                tv = TAUc * tv + x[(b * T + t) * NI + i];
                g_TIN[((size_t)t * B + b) * NI + i] = tv;
            }
        }
        return;
    }

    // ---------------- forward (+ output LIF + reverse filter + fused A), bids 0..63 ----------------
    float* ws   = (float*)smraw;            // NO*NH
    float* zsh  = ws + NO * NH;             // NH
    float* errh = zsh + NH;                 // T*NO (err, then EF in place)
    int*   list = (int*)(errh + T * NO);    // NH+64
    unsigned* zmask = (unsigned*)(list + NH + 64);   // 16

    int b = bid;
    int q = tid;
    int lane = tid & 31, w = tid >> 5;
    bool is_n = (tid < 128);
    int ow = w - 4;

    for (int i = tid; i < NO * NH; i += 256) ws[i] = wout[i];
    for (int i = tid; i < NH; i += 256) zsh[i] = 0.f;
    __syncthreads();

    const float4* wrec4 = (const float4*)wrec;
    float4 hm = {0,0,0,0}, tr = {0,0,0,0}, zs = {0,0,0,0};
    float om[5] = {}, os[5] = {};
    int nact = 0, pdone = -1;

    auto do_out = [&](int tp) {
#pragma unroll
        for (int qq = 0; qq < 5; qq++) {
            int o = ow * 5 + qq;
            float s = 0.f;
#pragma unroll
            for (int c = 0; c < 16; c++)
                s += zsh[c * 32 + lane] * ws[o * NH + c * 32 + lane];
#pragma unroll
            for (int off = 16; off; off >>= 1) s += __shfl_xor_sync(0xffffffffu, s, off);
            om[qq] = TAUc * om[qq] * (1.f - os[qq]) + s;
            os[qq] = (om[qq] >= THRc) ? 1.f : 0.f;
            if (lane == 0) {
                out[((size_t)b * T + tp) * NO + o] = os[qq];
                errh[tp * NO + o] = os[qq] - label[((size_t)b * T + tp) * NO + o];
            }
        }
    };

    for (int t = 0; t < T; t++) {
        float4 z = {0,0,0,0};
        unsigned nib = 0;
        if (is_n) {
            int p = t >> 1;
            if (p > pdone) {
                unsigned thr = (p < 8) ? 8u : 4u;
                while (((volatile unsigned*)g_ready)[p] < thr) {}
                pdone = p;
            }
            float4 xp;
            {
                const float4* xp4 = (const float4*)&g_XP[((size_t)t * B + b) * NH] + q;
                xp.x = __ldcg(&xp4->x); xp.y = __ldcg(&xp4->y);
                xp.z = __ldcg(&xp4->z); xp.w = __ldcg(&xp4->w);
            }
            // ---- dual-window pipelined gather, 12 rows/window, packed f32x2 adds ----
            // Summation order: strictly ascending row index (zero-pads past nact are
            // bit-neutral) -> identical spike trajectory.
            unsigned long long accL = 0ull, accH = 0ull;
            if (nact > 0) {
                float4 v0[12], v1[12];
                auto ldwin = [&](int base, float4* v) {
#pragma unroll
                    for (int u = 0; u < 12; u++) {
                        int ix = base + u;
                        float4 zz = {0.f, 0.f, 0.f, 0.f};
                        v[u] = (ix < nact) ? __ldg(&wrec4[(size_t)list[ix] * 128 + q]) : zz;
                    }
                };
                auto sumwin = [&](const float4* v) {
#pragma unroll
                    for (int u = 0; u < 12; u++) {
                        fadd2(accL, pk2(v[u].x, v[u].y));
                        fadd2(accH, pk2(v[u].z, v[u].w));
                    }
                };
                int npair = (nact + 23) / 24;
                ldwin(0, v0);
                for (int pp = 0; pp < npair; pp++) {
                    ldwin(pp * 24 + 12, v1);
                    sumwin(v0);                  // rows pp*24 .. +11
                    ldwin(pp * 24 + 24, v0);     // next pair (predicated past nact)
                    sumwin(v1);                  // rows pp*24+12 .. +23
                }
            }
            float4 acc;
            upk2(acc.x, acc.y, accL);
            upk2(acc.z, acc.w, accH);

            float4 ht;
            hm.x = TAUc * hm.x * (1.f - zs.x) + xp.x + acc.x;
            hm.y = TAUc * hm.y * (1.f - zs.y) + xp.y + acc.y;
            hm.z = TAUc * hm.z * (1.f - zs.z) + xp.z + acc.z;
            hm.w = TAUc * hm.w * (1.f - zs.w) + xp.w + acc.w;
            z.x = (hm.x >= THRc) ? 1.f : 0.f;
            z.y = (hm.y >= THRc) ? 1.f : 0.f;
            z.z = (hm.z >= THRc) ? 1.f : 0.f;
            z.w = (hm.w >= THRc) ? 1.f : 0.f;
            ht.x = TAUc * fmaxf(0.f, 1.f - fabsf((hm.x - THRc) * (1.f / THRc)));
            ht.y = TAUc * fmaxf(0.f, 1.f - fabsf((hm.y - THRc) * (1.f / THRc)));
            ht.z = TAUc * fmaxf(0.f, 1.f - fabsf((hm.z - THRc) * (1.f / THRc)));
            ht.w = TAUc * fmaxf(0.f, 1.f - fabsf((hm.w - THRc) * (1.f / THRc)));
            tr.x = TAUc * tr.x + zs.x;
            tr.y = TAUc * tr.y + zs.y;
            tr.z = TAUc * tr.z + zs.z;
            tr.w = TAUc * tr.w + zs.w;
            size_t o4 = ((size_t)t * B + b) * 128 + q;
            ((float4*)g_Z)[o4] = z; ((float4*)g_HT)[o4] = ht; ((float4*)g_TREC)[o4] = tr;
            zs = z;

            nib = (z.x != 0.f ? 1u : 0u) | (z.y != 0.f ? 2u : 0u)
                | (z.z != 0.f ? 4u : 0u) | (z.w != 0.f ? 8u : 0u);
            unsigned word = nib << ((lane & 7) * 4);
            word |= __shfl_xor_sync(0xffffffffu, word, 1);
            word |= __shfl_xor_sync(0xffffffffu, word, 2);
            word |= __shfl_xor_sync(0xffffffffu, word, 4);
            if ((lane & 7) == 0) zmask[w * 4 + (lane >> 3)] = word;
        } else if (w >= 4 && t > 0) {
            do_out(t - 1);
        }
        __syncthreads();

        if (is_n) {
            *(float4*)&zsh[4 * q] = z;
            int tot = 0, pre = 0;
            int myc = q >> 3;
#pragma unroll
            for (int c = 0; c < 16; c++) {
                int pc = __popc(zmask[c]);
                if (c < myc) pre += pc;
                tot += pc;
            }
            pre += __popc(zmask[myc] & ((1u << ((q & 7) * 4)) - 1u));
            nact = tot;
            if (nib & 1u) list[pre++] = 4 * q + 0;
            if (nib & 2u) list[pre++] = 4 * q + 1;
            if (nib & 4u) list[pre++] = 4 * q + 2;
            if (nib & 8u) list[pre++] = 4 * q + 3;
        }
        __syncthreads();
    }
    if (!is_n && w >= 4) do_out(T - 1);
    __syncthreads();

    // reverse kappa filter (EF written to errh in place + g_EF)
    if (tid < NO) {
        float ef = 0.f;
        for (int t = T - 1; t >= 0; t--) {
            ef = errh[t * NO + tid] + KAPc * ef;
            errh[t * NO + tid] = ef;
            g_EF[((size_t)t * B + b) * NO + tid] = ef;
        }
    }
    __syncthreads();

    // fused A: A[t*B+b, r] = (EF[t,:] . wout[:,r]) * HT[t*B+b, r]
    for (int e = tid; e < T * NH; e += 256) {
        int t = e >> 9, r = e & (NH - 1);
        const float* ef = errh + t * NO;
        float L = 0.f;
#pragma unroll
        for (int o = 0; o < NO; o++) L += ef[o] * ws[o * NH + r];
        size_t m = (size_t)t * B + b;
        g_A[m * NH + r] = L * g_HT[m * NH + r];
    }
}

// ---------------- gemm bodies (device) ----------------
__device__ __forceinline__ void gemm128_body(
    const float* __restrict__ A, int sA,
    const float* __restrict__ Bm, int sB,
    float* __restrict__ C, int N,
    int m0, int n0, int kts, int kte,
    float* __restrict__ As, float* __restrict__ Bs)
{
    int tid = threadIdx.x, tx = tid & 15, ty = tid >> 4;
    unsigned long long acc2[8][4];
#pragma unroll
    for (int ii = 0; ii < 8; ii++)
#pragma unroll
        for (int jj = 0; jj < 4; jj++) acc2[ii][jj] = 0ull;
    float4 va[2], vb[2];

    auto ldtile = [&](int kt) {
        int k0 = kt * 16;
#pragma unroll
        for (int rep = 0; rep < 2; rep++) {
            int f = tid + rep * 256;
            int kk = f >> 5, c4 = (f & 31) * 4;
            va[rep] = *(const float4*)&A[(size_t)(k0 + kk) * sA + m0 + c4];
            int n = n0 + c4;
            const float* bp = &Bm[(size_t)(k0 + kk) * sB + n];
            float4 bv;
            if (n + 3 < N) bv = *(const float4*)bp;
            else {
                bv.x = (n + 0 < N) ? bp[0] : 0.f;
                bv.y = (n + 1 < N) ? bp[1] : 0.f;
                bv.z = (n + 2 < N) ? bp[2] : 0.f;
                bv.w = (n + 3 < N) ? bp[3] : 0.f;
            }
            vb[rep] = bv;
        }
    };
    auto sttile = [&]() {
#pragma unroll
        for (int rep = 0; rep < 2; rep++) {
            int f = tid + rep * 256;
            int kk = f >> 5, c4 = (f & 31) * 4;
            *(float4*)&As[kk * 128 + c4] = va[rep];
            *(float4*)&Bs[kk * 128 + c4] = vb[rep];
        }
    };

    ldtile(kts);
    for (int kt = kts; kt < kte; kt++) {
        sttile();
        __syncthreads();
        if (kt + 1 < kte) ldtile(kt + 1);
#pragma unroll
        for (int k = 0; k < 16; k++) {
            float a[8], bb[8];
            *(float4*)&a[0]  = *(float4*)&As[k * 128 + ty * 4];
            *(float4*)&a[4]  = *(float4*)&As[k * 128 + 64 + ty * 4];
            *(float4*)&bb[0] = *(float4*)&Bs[k * 128 + tx * 4];
            *(float4*)&bb[4] = *(float4*)&Bs[k * 128 + 64 + tx * 4];
            unsigned long long b2[4];
#pragma unroll
            for (int jj = 0; jj < 4; jj++) b2[jj] = pk2(bb[2 * jj], bb[2 * jj + 1]);
#pragma unroll
            for (int ii = 0; ii < 8; ii++) {
                unsigned long long a2 = pk2(a[ii], a[ii]);
#pragma unroll
                for (int jj = 0; jj < 4; jj++) ffma2(acc2[ii][jj], a2, b2[jj]);
            }
        }
        __syncthreads();
    }
#pragma unroll
    for (int ii = 0; ii < 8; ii++) {
        int m = m0 + ((ii < 4) ? ty * 4 + ii : 64 + ty * 4 + (ii - 4));
        float av[8];
#pragma unroll
        for (int jj = 0; jj < 4; jj++) upk2(av[2 * jj], av[2 * jj + 1], acc2[ii][jj]);
#pragma unroll
        for (int j = 0; j < 8; j++) {
            int n = n0 + ((j < 4) ? tx * 4 + j : 64 + tx * 4 + (j - 4));
            if (n < N) C[(size_t)m * N + n] = av[j];
        }
    }
}

__device__ __forceinline__ void gemm64_body(
    const float* __restrict__ A, int sA,
    const float* __restrict__ Bm, int sB,
    float* __restrict__ C, int M, int N,
    int m0, int n0, int k0s, int k0e,
    float* __restrict__ As, float* __restrict__ Bs)
{
    int tid = threadIdx.x, tx = tid & 15, ty = tid >> 4;
    float acc[4][4] = {};
    for (int k0 = k0s; k0 < k0e; k0 += 16) {
#pragma unroll
        for (int rep = 0; rep < 4; rep++) {
            int e = tid + rep * 256;
            int mm = e & 63, kk = e >> 6;
            int mg = m0 + mm;
            As[kk * 64 + mm] = (mg < M) ? A[(size_t)(k0 + kk) * sA + mg] : 0.f;
            int ng = n0 + mm;
            Bs[kk * 64 + mm] = (ng < N) ? Bm[(size_t)(k0 + kk) * sB + ng] : 0.f;
        }
        __syncthreads();
#pragma unroll
        for (int k = 0; k < 16; k++) {
            float a[4], bb[4];
#pragma unroll
            for (int i = 0; i < 4; i++) a[i]  = As[k * 64 + ty * 4 + i];
#pragma unroll
            for (int j = 0; j < 4; j++) bb[j] = Bs[k * 64 + tx * 4 + j];
#pragma unroll
            for (int i = 0; i < 4; i++)
#pragma unroll
                for (int j = 0; j < 4; j++) acc[i][j] += a[i] * bb[j];
        }
        __syncthreads();
    }
#pragma unroll
    for (int i = 0; i < 4; i++) {
        int m = m0 + ty * 4 + i;
        if (m < M) {
#pragma unroll
            for (int j = 0; j < 4; j++) {
                int n = n0 + tx * 4 + j;
                if (n < N) C[(size_t)m * N + n] = acc[i][j];
            }
        }
    }
}

// ---------------- fused gradients: gf(168) + gr(128) + go(64) = 360 blocks ----------------
__global__ __launch_bounds__(256, 2) void k_grads() {
    __shared__ float As[16 * 128];
    __shared__ float Bs[16 * 128];
    int bid = blockIdx.x;
    if (bid < 168) {
        int z = bid / 24, rem = bid - z * 24;
        int n0 = (rem % 6) * 128, m0 = (rem / 6) * 128;
        const int kst[8] = {0, 57, 114, 171, 228, 285, 342, 400};
        gemm128_body(g_A, NH, g_TIN, NI,
                     g_gp + GFP_OFF + (size_t)z * GF_MN, NI,
                     m0, n0, kst[z], kst[z + 1], As, Bs);
    } else if (bid < 296) {
        int i = bid - 168;
        int z = i / 16, rem = i - z * 16;
        int n0 = (rem % 4) * 128, m0 = (rem / 4) * 128;
        gemm128_body(g_A, NH, g_TREC, NH,
                     g_gp + GRP_OFF + (size_t)z * GR_MN, NH,
                     m0, n0, z * 50, z * 50 + 50, As, Bs);
    } else {
        int i = bid - 296;
        int z = i / 8, nx = i - z * 8;
        gemm64_body(g_EF, NO, g_Z, NH,
                    g_gp + GOP_OFF + (size_t)z * GO_MN, NO, NH,
                    0, nx * 64, z * 800, z * 800 + 800, As, Bs);
    }
}

// ---------------- fused reduce over all three gradient outputs ----------------
__global__ void k_redAll(float* __restrict__ gf, float* __restrict__ gr,
                         float* __restrict__ go) {
    int i = blockIdx.x * 256 + threadIdx.x;
    if (i < GF_MN) {
        float s = 0.f;
#pragma unroll
        for (int z = 0; z < 7; z++) s += g_gp[GFP_OFF + (size_t)z * GF_MN + i];
        gf[i] = LRc * s;
    } else if (i < GF_MN + GR_MN) {
        int j = i - GF_MN;
        float s = 0.f;
#pragma unroll
        for (int z = 0; z < 8; z++) s += g_gp[GRP_OFF + (size_t)z * GR_MN + j];
        gr[j] = LRc * s;
    } else if (i < GF_MN + GR_MN + GO_MN) {
        int j = i - GF_MN - GR_MN;
        float s = 0.f;
#pragma unroll
        for (int z = 0; z < 8; z++) s += g_gp[GOP_OFF + (size_t)z * GO_MN + j];
        go[j] = LRc * s;
    }
}

// ---------------- launch ----------------
extern "C" void kernel_launch(void* const* d_in, const int* in_sizes, int n_in,
                              void* d_out, int out_size) {
    const float* x     = (const float*)d_in[0];
    const float* label = (const float*)d_in[1];
    const float* w1    = (const float*)d_in[3];
    const float* wrec  = (const float*)d_in[4];
    const float* wout  = (const float*)d_in[5];
    float* out = (float*)d_out;
    float* gf = out + B * T * NO;          // [NH, NI]
    float* gr = gf + NH * NI;              // [NH, NH]
    float* go = gr + NH * NH;              // [NO, NH]

    cudaFuncSetAttribute(k_main, cudaFuncAttributeMaxDynamicSharedMemorySize, MAIN_SMEM);

    void* pR;
    cudaGetSymbolAddress(&pR, g_ready);
    cudaMemsetAsync(pR, 0, 64 * sizeof(unsigned));

    k_main<<<471, 256, MAIN_SMEM>>>(x, w1, wrec, wout, label, out);
    k_grads<<<360, 256>>>();
    k_redAll<<<(GF_MN + GR_MN + GO_MN + 255) / 256, 256>>>(gf, gr, go);
}